// round 11
// baseline (speedup 1.0000x reference)
#include <cuda_runtime.h>
#include <cuda_bf16.h>
#include <cstdint>

#define NN      16384
#define NE_     1024
#define BB      16
#define KK      64
#define TX_     768
#define OM_     511
#define DD      512
#define SLOPE_  0.3f
#define E_INT_MAX 131072
#define E_FULL_MAX 262144

// ------------------------- helpers ------------------------------------------
__device__ __forceinline__ uint32_t smem_to_u32(const void* p) {
    uint32_t a;
    asm("{ .reg .u64 t; cvta.to.shared.u64 t, %1; cvt.u32.u64 %0, t; }"
        : "=r"(a) : "l"(p));
    return a;
}

#define CP_ASYNC16(saddr, gptr) \
    asm volatile("cp.async.cg.shared.global [%0], [%1], 16;" \
                 :: "r"(saddr), "l"(gptr) : "memory")

#define LDMX4(r0, r1, r2, r3, addr) \
    asm volatile("ldmatrix.sync.aligned.m8n8.x4.shared.b16 {%0,%1,%2,%3}, [%4];" \
                 : "=r"(r0), "=r"(r1), "=r"(r2), "=r"(r3) : "r"(addr))

#define MMA16816(c, a, b) \
    asm volatile("mma.sync.aligned.m16n8k16.row.col.f32.bf16.bf16.f32 " \
                 "{%0,%1,%2,%3},{%4,%5,%6,%7},{%8,%9},{%0,%1,%2,%3};" \
                 : "+f"((c)[0]), "+f"((c)[1]), "+f"((c)[2]), "+f"((c)[3]) \
                 : "r"((a)[0]), "r"((a)[1]), "r"((a)[2]), "r"((a)[3]), \
                   "r"((b)[0]), "r"((b)[1]))

// ------------------------- scratch (device globals) -------------------------
__device__ __nv_bfloat16 g_A1H[NN * DD];       // x split; later ZK split
__device__ __nv_bfloat16 g_A1L[NN * DD];
__device__ __nv_bfloat16 g_A2H[NN * DD];       // omic split; later Zg split
__device__ __nv_bfloat16 g_A2L[NN * DD];
__device__ __nv_bfloat16 g_CHH[NN * DD];       // pre_x split
__device__ __nv_bfloat16 g_CHL[NN * DD];
__device__ __nv_bfloat16 g_E1H[2048 * TX_];    // entity emb split (name|desc)
__device__ __nv_bfloat16 g_E1L[2048 * TX_];
__device__ __nv_bfloat16 g_E2H[NE_ * 1536];    // entity linears split
__device__ __nv_bfloat16 g_E2L[NE_ * 1536];
#define WT_TOTAL 3801088
__device__ __nv_bfloat16 g_WH[WT_TOTAL];
__device__ __nv_bfloat16 g_WL[WT_TOTAL];
__device__ __nv_bfloat16 g_WFH[DD * DD];       // WFT split (ienc fold)
__device__ __nv_bfloat16 g_WFL[DD * DD];
__device__ __nv_bfloat16 g_NDPH[NE_ * DD];     // ndpart split
__device__ __nv_bfloat16 g_NDPL[NE_ * DD];
__device__ float g_NDP2[NE_ * DD];             // ndpart @ Wienc'
__device__ float g_B2  [2 * DD];               // [pre_b@Wenc | preW511@Wenc]
__device__ float g_M   [NN * DD];              // message buffer (ienc, then enc)
__device__ float g_MP  [NN * DD];              // M_pre = pre-fold part of enc msg
__device__ float g_ZK  [NE_ * DD];
__device__ float g_KO  [NN];
__device__ float g_SC  [BB * KK];
__device__ int   g_CNT[2 * NN];
__device__ int   g_OFF[2 * NN];
__device__ int   g_CUR[2 * NN];
__device__ int   g_SRT[E_INT_MAX + E_FULL_MAX];

// ============================================================================
// HMMA split-bf16 GEMM (calibrated core)
// flags: 1 leaky, 2 accumulate (+Cin), 4 add gat[(row&1023)*512+col],
//        8 write split-bf16 (Oh/Ol stride ldo, zero-pad cols [Nc,padN)),
//        16 skip fp32 C write, 32 add koV[row]*w511[col],
//        64 gate fusion: atomicAdd(C[row*ldc], sum_col tanh(v)*w511[col])
// ============================================================================
__global__ void __launch_bounds__(256, 2)
hgemm(const __nv_bfloat16* __restrict__ Ah, const __nv_bfloat16* __restrict__ Al,
      const __nv_bfloat16* __restrict__ Bh, const __nv_bfloat16* __restrict__ Bl,
      const float* __restrict__ bias, const float* __restrict__ gat,
      const float* __restrict__ koV, const float* __restrict__ w511,
      const float* __restrict__ Cin, float* __restrict__ C,
      __nv_bfloat16* __restrict__ Oh, __nv_bfloat16* __restrict__ Ol,
      int lda_b, int ldb_b, int nchunks, int Nc, int ldc, int ldo,
      int padN, int flags)
{
    extern __shared__ char smem[];
    const uint32_t sb = smem_to_u32(smem);
    const int tid  = threadIdx.x;
    const int lane = tid & 31;
    const int wid  = tid >> 5;
    const int wm   = (wid >> 2) * 64;
    const int wn   = (wid & 3) * 32;
    const int bm   = blockIdx.y * 128;
    const int bn   = blockIdx.x * 128;

    float acc[4][4][4];
#pragma unroll
    for (int i = 0; i < 4; i++)
#pragma unroll
        for (int j = 0; j < 4; j++)
#pragma unroll
            for (int q = 0; q < 4; q++) acc[i][j][q] = 0.f;

    auto load_stage = [&](int st, int k0) {
        const uint32_t base = sb + st * 40960;
#pragma unroll
        for (int i = 0; i < 2; i++) {
            const int idx = tid + i * 256;
            const int row = idx >> 2;
            const int c16 = idx & 3;
            const uint32_t so = base + row * 80 + c16 * 16;
            const size_t ga = (size_t)(bm + row) * lda_b + k0 + c16 * 8;
            const size_t gb = (size_t)(bn + row) * ldb_b + k0 + c16 * 8;
            CP_ASYNC16(so,          Ah + ga);
            CP_ASYNC16(so + 10240,  Al + ga);
            CP_ASYNC16(so + 20480,  Bh + gb);
            CP_ASYNC16(so + 30720,  Bl + gb);
        }
        asm volatile("cp.async.commit_group;" ::: "memory");
    };

    auto compute = [&](int st) {
        const uint32_t base = sb + st * 40960;
        const int arow = lane & 15;
        const int asub = (lane >> 4) * 8;
        const int brow = (lane & 7) + (lane >> 4) * 8;
        const int bsub = ((lane >> 3) & 1) * 8;
#pragma unroll
        for (int ks = 0; ks < 2; ks++) {
            const int kb = ks * 16;
            const uint32_t a0 = base + ((wm + arow) * 40 + kb + asub) * 2;
            const uint32_t b0 = base + 20480 + ((wn + brow) * 40 + kb + bsub) * 2;

            uint32_t ah[4][4], bh[4][2];
#pragma unroll
            for (int mt = 0; mt < 4; mt++)
                LDMX4(ah[mt][0], ah[mt][1], ah[mt][2], ah[mt][3], a0 + mt * 16 * 80);
#pragma unroll
            for (int p = 0; p < 2; p++)
                LDMX4(bh[2*p][0], bh[2*p][1], bh[2*p+1][0], bh[2*p+1][1],
                      b0 + p * 16 * 80);
#pragma unroll
            for (int mt = 0; mt < 4; mt++)
#pragma unroll
                for (int nt = 0; nt < 4; nt++)
                    MMA16816(acc[mt][nt], ah[mt], bh[nt]);
#pragma unroll
            for (int p = 0; p < 2; p++) {
                uint32_t bl[2][2];
                LDMX4(bl[0][0], bl[0][1], bl[1][0], bl[1][1],
                      b0 + 10240 + p * 16 * 80);
#pragma unroll
                for (int mt = 0; mt < 4; mt++) {
                    MMA16816(acc[mt][2*p],   ah[mt], bl[0]);
                    MMA16816(acc[mt][2*p+1], ah[mt], bl[1]);
                }
            }
#pragma unroll
            for (int mt = 0; mt < 4; mt++) {
                uint32_t al[4];
                LDMX4(al[0], al[1], al[2], al[3], a0 + 10240 + mt * 16 * 80);
#pragma unroll
                for (int nt = 0; nt < 4; nt++)
                    MMA16816(acc[mt][nt], al, bh[nt]);
            }
        }
    };

    load_stage(0, 0);
    for (int c = 0; c < nchunks; c++) {
        if (c + 1 < nchunks) {
            load_stage((c + 1) & 1, (c + 1) * 32);
            asm volatile("cp.async.wait_group 1;" ::: "memory");
        } else {
            asm volatile("cp.async.wait_group 0;" ::: "memory");
        }
        __syncthreads();
        compute(c & 1);
        __syncthreads();
    }

    // ---- epilogue ----
    const int er = lane >> 2;
    const int ec = (lane & 3) * 2;
#pragma unroll
    for (int mt = 0; mt < 4; mt++) {
#pragma unroll
        for (int h = 0; h < 2; h++) {
            const int row = bm + wm + mt * 16 + er + h * 8;
            const size_t crow = (size_t)row * ldc;
            const size_t orow = (size_t)row * ldo;
            const size_t grow = (size_t)(row & (NE_ - 1)) * 512;
            const float kv = (flags & 32) ? koV[row] : 0.f;
            float rp = 0.f;
#pragma unroll
            for (int nt = 0; nt < 4; nt++) {
                const int col = bn + wn + nt * 8 + ec;
                float v0 = acc[mt][nt][h * 2 + 0];
                float v1 = acc[mt][nt][h * 2 + 1];
                if (col + 1 < Nc) {
                    if (bias) {
                        float2 bb = *reinterpret_cast<const float2*>(bias + col);
                        v0 += bb.x; v1 += bb.y;
                    }
                    if (flags & 4) {
                        float2 gg = *reinterpret_cast<const float2*>(gat + grow + col);
                        v0 += gg.x; v1 += gg.y;
                    }
                    if (flags & 32) {
                        float2 ww = *reinterpret_cast<const float2*>(w511 + col);
                        v0 += kv * ww.x; v1 += kv * ww.y;
                    }
                    if (flags & 1) {
                        v0 = v0 > 0.f ? v0 : SLOPE_ * v0;
                        v1 = v1 > 0.f ? v1 : SLOPE_ * v1;
                    }
                    if (flags & 2) {
                        float2 ci = *reinterpret_cast<const float2*>(Cin + crow + col);
                        v0 += ci.x; v1 += ci.y;
                    }
                    if (flags & 64) {
                        float2 w2c = *reinterpret_cast<const float2*>(w511 + col);
                        rp = fmaf(tanhf(v0), w2c.x, rp);
                        rp = fmaf(tanhf(v1), w2c.y, rp);
                    }
                    if (!(flags & 16))
                        *reinterpret_cast<float2*>(C + crow + col) = make_float2(v0, v1);
                    if (flags & 8) {
                        __nv_bfloat16 h0 = __float2bfloat16(v0);
                        __nv_bfloat16 h1 = __float2bfloat16(v1);
                        __nv_bfloat162 hh; hh.x = h0; hh.y = h1;
                        __nv_bfloat162 ll;
                        ll.x = __float2bfloat16(v0 - __bfloat162float(h0));
                        ll.y = __float2bfloat16(v1 - __bfloat162float(h1));
                        *reinterpret_cast<__nv_bfloat162*>(Oh + orow + col) = hh;
                        *reinterpret_cast<__nv_bfloat162*>(Ol + orow + col) = ll;
                    }
                } else {
                    float vv[2] = {v0, v1};
#pragma unroll
                    for (int q = 0; q < 2; q++) {
                        const int cq = col + q;
                        if (cq < Nc) {
                            float v = vv[q];
                            if (bias)       v += bias[cq];
                            if (flags & 4)  v += gat[grow + cq];
                            if (flags & 32) v += kv * w511[cq];
                            if (flags & 1)  v = v > 0.f ? v : SLOPE_ * v;
                            if (flags & 2)  v += Cin[crow + cq];
                            if (flags & 64) rp = fmaf(tanhf(v), w511[cq], rp);
                            if (!(flags & 16)) C[crow + cq] = v;
                            if (flags & 8) {
                                __nv_bfloat16 hh = __float2bfloat16(v);
                                Oh[orow + cq] = hh;
                                Ol[orow + cq] = __float2bfloat16(v - __bfloat162float(hh));
                            }
                        } else if ((flags & 8) && cq < padN) {
                            Oh[orow + cq] = __float2bfloat16(0.f);
                            Ol[orow + cq] = __float2bfloat16(0.f);
                        }
                    }
                }
            }
            if (flags & 64) {
                rp += __shfl_xor_sync(0xffffffffu, rp, 1);
                rp += __shfl_xor_sync(0xffffffffu, rp, 2);
                if ((lane & 3) == 0) atomicAdd(&C[crow], rp);
            }
        }
    }
}

// ------------------------- conversion kernels -------------------------------
__global__ void cvt_splitA(const float* __restrict__ A, int M, int K, int lda,
                           int width, int ldrow,
                           __nv_bfloat16* __restrict__ Ah, __nv_bfloat16* __restrict__ Al)
{
    int i = blockIdx.x * blockDim.x + threadIdx.x;
    int half = width >> 1;
    int r = i / half;
    if (r >= M) return;
    int c2 = (i - r * half) * 2;
    float v0 = (c2 < K)     ? A[(size_t)r * lda + c2]     : 0.f;
    float v1 = (c2 + 1 < K) ? A[(size_t)r * lda + c2 + 1] : 0.f;
    __nv_bfloat16 h0 = __float2bfloat16(v0), h1 = __float2bfloat16(v1);
    __nv_bfloat16 l0 = __float2bfloat16(v0 - __bfloat162float(h0));
    __nv_bfloat16 l1 = __float2bfloat16(v1 - __bfloat162float(h1));
    __nv_bfloat162 hh; hh.x = h0; hh.y = h1;
    __nv_bfloat162 ll; ll.x = l0; ll.y = l1;
    *reinterpret_cast<__nv_bfloat162*>(Ah + (size_t)r * ldrow + c2) = hh;
    *reinterpret_cast<__nv_bfloat162*>(Al + (size_t)r * ldrow + c2) = ll;
}

struct WJobs {
    const float* W[9];
    long off[9];
    long cum[10];
    int K[9], N[9], ldw[9], ldo[9], trans[9];
    int njobs;
};

__global__ void cvt_splitW_all(WJobs jobs,
                               __nv_bfloat16* __restrict__ Wh,
                               __nv_bfloat16* __restrict__ Wl)
{
    long gid = (long)blockIdx.x * blockDim.x + threadIdx.x;
    if (gid >= jobs.cum[jobs.njobs]) return;
    int j = 0;
    while (gid >= jobs.cum[j + 1]) j++;
    long local = gid - jobs.cum[j];
    int ldo = jobs.ldo[j];
    int n = (int)(local / ldo);
    int k = (int)(local - (long)n * ldo);
    float v = 0.f;
    if (n < jobs.N[j] && k < jobs.K[j])
        v = jobs.trans[j] ? jobs.W[j][(size_t)k * jobs.ldw[j] + n]
                          : jobs.W[j][(size_t)n * jobs.ldw[j] + k];
    __nv_bfloat16 h = __float2bfloat16(v);
    Wh[jobs.off[j] + local] = h;
    Wl[jobs.off[j] + local] = __float2bfloat16(v - __bfloat162float(h));
}

// B2[0,:] = pre_b @ enc_W ; B2[1,:] = pre_W[511,:] @ enc_W
__global__ void fold_bias(const float* __restrict__ pre_b, const float* __restrict__ pre_W,
                          const float* __restrict__ enc_W, float* __restrict__ B2)
{
    int n = threadIdx.x;
    int which = blockIdx.x;
    const float* v = which ? (pre_W + (size_t)511 * DD) : pre_b;
    float acc = 0.f;
    for (int j = 0; j < DD; j++)
        acc = fmaf(v[j], enc_W[(size_t)j * DD + n], acc);
    B2[which * DD + n] = acc;
}

// ------------------------- misc ----------------------------------------------
__global__ void zero_f(float* __restrict__ p, int n)
{ int i = blockIdx.x * blockDim.x + threadIdx.x; if (i < n) p[i] = 0.f; }
__global__ void zero_i(int* __restrict__ p, int n)
{ int i = blockIdx.x * blockDim.x + threadIdx.x; if (i < n) p[i] = 0; }

// also zeroes the gate-score accumulator (BB*KK == grid coverage)
__global__ void set_ko(const int* __restrict__ bkm, float* __restrict__ ko,
                       float* __restrict__ sc)
{
    int i = blockIdx.x * blockDim.x + threadIdx.x;
    if (i < BB * KK) {
        ko[(i >> 6) * NE_ + bkm[i]] = 1.0f;
        sc[i] = 0.f;
    }
}

// ------------------------- CSR build -----------------------------------------
__global__ void csr_count2(const int* __restrict__ iei, int Ei,
                           const int* __restrict__ fei, int Ef,
                           int* __restrict__ cnt)
{
    int i = blockIdx.x * blockDim.x + threadIdx.x;
    if (i < Ei) atomicAdd(&cnt[iei[Ei + i]], 1);
    else if (i < Ei + Ef) {
        int j = i - Ei;
        atomicAdd(&cnt[NN + fei[Ef + j]], 1);
    }
}

__global__ void __launch_bounds__(1024, 1)
csr_scan2(const int* __restrict__ cnt, int* __restrict__ off,
          int* __restrict__ cur, int base1)
{
    __shared__ int sa[1024], sbuf[1024];
    const int g = blockIdx.x;
    const int* c = cnt + g * NN;
    int* o = off + g * NN;
    int* u = cur + g * NN;
    int t = threadIdx.x;
    int base = t * 16;
    int loc[16];
    int s = 0;
#pragma unroll
    for (int j = 0; j < 16; j++) { loc[j] = c[base + j]; s += loc[j]; }
    sa[t] = s;
    __syncthreads();
    int* A = sa; int* Bf = sbuf;
    for (int d = 1; d < 1024; d <<= 1) {
        int v = A[t] + (t >= d ? A[t - d] : 0);
        __syncthreads();
        Bf[t] = v;
        __syncthreads();
        int* tmp = A; A = Bf; Bf = tmp;
    }
    int run = (t ? A[t - 1] : 0) + (g ? base1 : 0);
#pragma unroll
    for (int j = 0; j < 16; j++) { o[base + j] = run; u[base + j] = run; run += loc[j]; }
}

__global__ void csr_fill2(const int* __restrict__ iei, int Ei,
                          const int* __restrict__ fei, int Ef,
                          int* __restrict__ cur, int* __restrict__ srt)
{
    int i = blockIdx.x * blockDim.x + threadIdx.x;
    if (i < Ei) {
        int p = atomicAdd(&cur[iei[Ei + i]], 1);
        srt[p] = iei[i];
    } else if (i < Ei + Ef) {
        int j = i - Ei;
        int p = atomicAdd(&cur[NN + fei[Ef + j]], 1);
        srt[p] = fei[j];
    }
}

// gconv(int): Zg = leaky(M[r]+b+sum) + x_c ; emit split bf16 (ld 512)
__global__ void __launch_bounds__(128, 8)
gconv_int(const float* __restrict__ m, const float* __restrict__ bias,
          const int* __restrict__ off, const int* __restrict__ cnt,
          const int* __restrict__ srt,
          const float* __restrict__ x, const float* __restrict__ ko,
          __nv_bfloat16* __restrict__ Oh, __nv_bfloat16* __restrict__ Ol)
{
    const int r = blockIdx.x;
    const int t = threadIdx.x;
    float4 acc = reinterpret_cast<const float4*>(m + (size_t)r * DD)[t];
    float4 b   = reinterpret_cast<const float4*>(bias)[t];
    acc.x += b.x; acc.y += b.y; acc.z += b.z; acc.w += b.w;
    const int s0 = off[r];
    const int d  = cnt[r];
    for (int e = 0; e < d; e++) {
        int s = srt[s0 + e];
        float4 v = reinterpret_cast<const float4*>(m + (size_t)s * DD)[t];
        acc.x += v.x; acc.y += v.y; acc.z += v.z; acc.w += v.w;
    }
    acc.x = acc.x > 0.f ? acc.x : SLOPE_ * acc.x;
    acc.y = acc.y > 0.f ? acc.y : SLOPE_ * acc.y;
    acc.z = acc.z > 0.f ? acc.z : SLOPE_ * acc.z;
    acc.w = acc.w > 0.f ? acc.w : SLOPE_ * acc.w;
    const int c0 = t * 4;
    float vv[4] = {acc.x, acc.y, acc.z, acc.w};
#pragma unroll
    for (int q = 0; q < 4; q++) {
        int c = c0 + q;
        vv[q] += (c < OM_) ? x[(size_t)r * OM_ + c] : ko[r];
    }
    __nv_bfloat16 h[4], l[4];
#pragma unroll
    for (int q = 0; q < 4; q++) {
        h[q] = __float2bfloat16(vv[q]);
        l[q] = __float2bfloat16(vv[q] - __bfloat162float(h[q]));
    }
    size_t o = (size_t)r * DD + c0;
    __nv_bfloat162 h01; h01.x = h[0]; h01.y = h[1];
    __nv_bfloat162 h23; h23.x = h[2]; h23.y = h[3];
    __nv_bfloat162 l01; l01.x = l[0]; l01.y = l[1];
    __nv_bfloat162 l23; l23.x = l[2]; l23.y = l[3];
    *reinterpret_cast<__nv_bfloat162*>(Oh + o)     = h01;
    *reinterpret_cast<__nv_bfloat162*>(Oh + o + 2) = h23;
    *reinterpret_cast<__nv_bfloat162*>(Ol + o)     = l01;
    *reinterpret_cast<__nv_bfloat162*>(Ol + o + 2) = l23;
}

// gconv(full) only at the 1024 gathered KO rows; fused gather_zk
__global__ void __launch_bounds__(128, 8)
gconv_rows(const float* __restrict__ m, const float* __restrict__ bias,
           const int* __restrict__ off, const int* __restrict__ cnt,
           const int* __restrict__ srt, const int* __restrict__ bkm,
           float* __restrict__ ZK,
           __nv_bfloat16* __restrict__ Ah, __nv_bfloat16* __restrict__ Al)
{
    const int i = blockIdx.x;
    const int t = threadIdx.x;
    const int r = bkm[i] + (i >> 6) * NE_;
    float4 acc = reinterpret_cast<const float4*>(m + (size_t)r * DD)[t];
    float4 b   = reinterpret_cast<const float4*>(bias)[t];
    acc.x += b.x; acc.y += b.y; acc.z += b.z; acc.w += b.w;
    const int s0 = off[r];
    const int d  = cnt[r];
    for (int e = 0; e < d; e++) {
        int s = srt[s0 + e];
        float4 v = reinterpret_cast<const float4*>(m + (size_t)s * DD)[t];
        acc.x += v.x; acc.y += v.y; acc.z += v.z; acc.w += v.w;
    }
    acc.x = acc.x > 0.f ? acc.x : SLOPE_ * acc.x;
    acc.y = acc.y > 0.f ? acc.y : SLOPE_ * acc.y;
    acc.z = acc.z > 0.f ? acc.z : SLOPE_ * acc.z;
    acc.w = acc.w > 0.f ? acc.w : SLOPE_ * acc.w;
    reinterpret_cast<float4*>(ZK + (size_t)i * DD)[t] = acc;
    float vv[4] = {acc.x, acc.y, acc.z, acc.w};
    __nv_bfloat16 h[4], l[4];
#pragma unroll
    for (int q = 0; q < 4; q++) {
        h[q] = __float2bfloat16(vv[q]);
        l[q] = __float2bfloat16(vv[q] - __bfloat162float(h[q]));
    }
    size_t o = (size_t)i * DD + t * 4;
    __nv_bfloat162 h01; h01.x = h[0]; h01.y = h[1];
    __nv_bfloat162 h23; h23.x = h[2]; h23.y = h[3];
    __nv_bfloat162 l01; l01.x = l[0]; l01.y = l[1];
    __nv_bfloat162 l23; l23.x = l[2]; l23.y = l[3];
    *reinterpret_cast<__nv_bfloat162*>(Ah + o)     = h01;
    *reinterpret_cast<__nv_bfloat162*>(Ah + o + 2) = h23;
    *reinterpret_cast<__nv_bfloat162*>(Al + o)     = l01;
    *reinterpret_cast<__nv_bfloat162*>(Al + o + 2) = l23;
}

// ------------------------- readout -------------------------------------------
__global__ void readout2(const float* __restrict__ ZK, const float* __restrict__ sc,
                         const float* __restrict__ b2,
                         const float* __restrict__ regW, const float* __restrict__ regb,
                         float* __restrict__ out)
{
    int b = blockIdx.x;
    int tid = threadIdx.x;
    __shared__ float w[KK];
    __shared__ float red[256];
    __shared__ float sm;
    if (tid < KK) w[tid] = sc[b * KK + tid] + b2[0];
    __syncthreads();
    if (tid == 0) {
        float m = w[0];
        for (int k = 1; k < KK; k++) m = fmaxf(m, w[k]);
        float s = 0.f;
        for (int k = 0; k < KK; k++) { w[k] = expf(w[k] - m); s += w[k]; }
        sm = s;
    }
    __syncthreads();
    int c0 = tid, c1 = tid + 256;
    float r0 = 0.f, r1 = 0.f;
    for (int k = 0; k < KK; k++) {
        const float* z = ZK + ((size_t)b * KK + k) * DD;
        float wk = w[k];
        r0 = fmaf(wk, z[c0], r0);
        r1 = fmaf(wk, z[c1], r1);
    }
    float part = (r0 * regW[c0] + r1 * regW[c1]) / sm;
    red[tid] = part;
    __syncthreads();
    for (int s = 128; s > 0; s >>= 1) {
        if (tid < s) red[tid] += red[tid + s];
        __syncthreads();
    }
    if (tid == 0) out[b] = red[0] + regb[0];
}

// ------------------------- host side ------------------------------------------
static const int HG_SMEM = 2 * 40960;

extern "C" void kernel_launch(void* const* d_in, const int* in_sizes, int n_in,
                              void* d_out, int out_size)
{
    int map_[31];
    {
        int p = 0;
        for (int l = 0; l < 31; l++) {
            if (l == 5 || l == 8) {
                bool present = (n_in == 31);
                if (present && p < n_in && in_sizes[p] == 1) map_[l] = p++;
                else map_[l] = -1;
            } else map_[l] = p++;
        }
    }
    auto F = [&](int l) -> const float* { return (const float*)d_in[map_[l]]; };
    auto I = [&](int l) -> const int*   { return (const int*)d_in[map_[l]]; };

    const float* x        = F(0);
    const float* pre_x    = F(1);
    const int*   edge_ei  = I(2);
    const int*   int_ei   = I(3);
    const float* name_emb = F(6);
    const float* desc_emb = F(7);
    const int*   bkm      = I(9);
    const float* name_W = F(11), *name_b = F(12);
    const float* desc_W = F(13), *desc_b = F(14);
    const float* omic_W = F(15), *omic_b = F(16);
    const float* fus_W  = F(17), *fus_b  = F(18);
    const float* pre_W  = F(19), *pre_b  = F(20);
    const float* ienc_W = F(21), *ienc_b = F(22);
    const float* enc_W  = F(23), *enc_b  = F(24);
    const float* gate_W1 = F(25), *gate_b1 = F(26);
    const float* gate_W2 = F(27), *gate_b2 = F(28);
    const float* reg_W   = F(29), *reg_b   = F(30);
    float* out = (float*)d_out;

    const int E_full = in_sizes[map_[2]] / 2;
    const int E_int  = in_sizes[map_[3]] / 2;
    const float* W2 = fus_W + (size_t)1536 * OM_;

    __nv_bfloat16 *pA1H, *pA1L, *pA2H, *pA2L, *pCHH, *pCHL, *pE1H, *pE1L, *pE2H, *pE2L;
    __nv_bfloat16 *pWH, *pWL, *pWFH, *pWFL, *pNDPH, *pNDPL;
    float *pNDP2, *pB2, *pM, *pMP, *pZK, *pKO, *pSC;
    int *pCNT, *pOFF, *pCUR, *pSRT;
    cudaGetSymbolAddress((void**)&pA1H, g_A1H);
    cudaGetSymbolAddress((void**)&pA1L, g_A1L);
    cudaGetSymbolAddress((void**)&pA2H, g_A2H);
    cudaGetSymbolAddress((void**)&pA2L, g_A2L);
    cudaGetSymbolAddress((void**)&pCHH, g_CHH);
    cudaGetSymbolAddress((void**)&pCHL, g_CHL);
    cudaGetSymbolAddress((void**)&pE1H, g_E1H);
    cudaGetSymbolAddress((void**)&pE1L, g_E1L);
    cudaGetSymbolAddress((void**)&pE2H, g_E2H);
    cudaGetSymbolAddress((void**)&pE2L, g_E2L);
    cudaGetSymbolAddress((void**)&pWH,  g_WH);
    cudaGetSymbolAddress((void**)&pWL,  g_WL);
    cudaGetSymbolAddress((void**)&pWFH, g_WFH);
    cudaGetSymbolAddress((void**)&pWFL, g_WFL);
    cudaGetSymbolAddress((void**)&pNDPH, g_NDPH);
    cudaGetSymbolAddress((void**)&pNDPL, g_NDPL);
    cudaGetSymbolAddress((void**)&pNDP2, g_NDP2);
    cudaGetSymbolAddress((void**)&pB2,  g_B2);
    cudaGetSymbolAddress((void**)&pM,   g_M);
    cudaGetSymbolAddress((void**)&pMP,  g_MP);
    cudaGetSymbolAddress((void**)&pZK,  g_ZK);
    cudaGetSymbolAddress((void**)&pKO,  g_KO);
    cudaGetSymbolAddress((void**)&pSC,  g_SC);
    cudaGetSymbolAddress((void**)&pCNT, g_CNT);
    cudaGetSymbolAddress((void**)&pOFF, g_OFF);
    cudaGetSymbolAddress((void**)&pCUR, g_CUR);
    cudaGetSymbolAddress((void**)&pSRT, g_SRT);

    cudaFuncSetAttribute(hgemm, cudaFuncAttributeMaxDynamicSharedMemorySize, HG_SMEM);

    const long OFF_NAME  = 0;        // 768x768  name^T
    const long OFF_DESC  = 589824;   // 768x768  desc^T
    const long OFF_FUS1  = 1179648;  // 512x1536 fus[0:1536]^T
    const long OFF_OMIC  = 1966080;  // 512x512  omic^T
    const long OFF_IENC2 = 2228224;  // 512x512  ienc'^T
    const long OFF_W2D   = 2490368;  // 512x512  fus2 direct
    const long OFF_PRED  = 2752512;  // 512x512  pre_W direct
    const long OFF_ENC2  = 3014656;  // 512x1024 [enc^T | WPE^T]
    const long OFF_GATE  = 3538944;  // 512x512  gate1^T

    cudaStream_t s1, s2, s3;
    cudaStreamCreateWithFlags(&s1, cudaStreamNonBlocking);
    cudaStreamCreateWithFlags(&s2, cudaStreamNonBlocking);
    cudaStreamCreateWithFlags(&s3, cudaStreamNonBlocking);
    cudaEvent_t evStart, evW, evX, evKO, ev1, ev2, ev3;
    cudaEventCreateWithFlags(&evStart, cudaEventDisableTiming);
    cudaEventCreateWithFlags(&evW,     cudaEventDisableTiming);
    cudaEventCreateWithFlags(&evX,     cudaEventDisableTiming);
    cudaEventCreateWithFlags(&evKO,    cudaEventDisableTiming);
    cudaEventCreateWithFlags(&ev1,     cudaEventDisableTiming);
    cudaEventCreateWithFlags(&ev2,     cudaEventDisableTiming);
    cudaEventCreateWithFlags(&ev3,     cudaEventDisableTiming);

    cudaEventRecord(evStart, 0);
    cudaStreamWaitEvent(s1, evStart, 0);
    cudaStreamWaitEvent(s2, evStart, 0);

    // ---------------- s2: x split | KO+SC | CSR | pre split | M_pre ---------
    cvt_splitA<<<(NN * 256 + 255) / 256, 256, 0, s2>>>(x, NN, OM_, OM_, 512, 512, pA1H, pA1L);
    cudaEventRecord(evX, s2);
    zero_f<<<(NN + 255) / 256, 256, 0, s2>>>(pKO, NN);
    set_ko<<<(BB * KK + 255) / 256, 256, 0, s2>>>(bkm, pKO, pSC);
    zero_i<<<(2 * NN + 255) / 256, 256, 0, s2>>>(pCNT, 2 * NN);
    csr_count2<<<(E_int + E_full + 255) / 256, 256, 0, s2>>>(int_ei, E_int, edge_ei, E_full, pCNT);
    csr_scan2<<<2, 1024, 0, s2>>>(pCNT, pOFF, pCUR, E_int);
    csr_fill2<<<(E_int + E_full + 255) / 256, 256, 0, s2>>>(int_ei, E_int, edge_ei, E_full, pCUR, pSRT);
    cudaEventRecord(evKO, s2);
    cvt_splitA<<<(NN * 256 + 255) / 256, 256, 0, s2>>>(pre_x, NN, OM_, OM_, 512, 512, pCHH, pCHL);

    // ---------------- s1: entity emb conversions (no weight dep) ----------
    cvt_splitA<<<(NE_ * 384 + 255) / 256, 256, 0, s1>>>(name_emb, NE_, TX_, TX_, TX_, TX_, pE1H, pE1L);
    cvt_splitA<<<(NE_ * 384 + 255) / 256, 256, 0, s1>>>(desc_emb, NE_, TX_, TX_, TX_, TX_,
                                                        pE1H + (size_t)NE_ * TX_,
                                                        pE1L + (size_t)NE_ * TX_);

    // ---------------- s0: weight conversion -------------------------------
    {
        WJobs jb;
        const float* Ws[9] = {name_W, desc_W, fus_W, omic_W, ienc_W, W2, pre_W, enc_W, gate_W1};
        int Ks[9]  = {TX_, TX_, 1536, OM_, OM_, OM_, DD, DD, DD};
        int Ns[9]  = {TX_, TX_, OM_, OM_, DD, OM_, DD, DD, DD};
        int ldw[9] = {TX_, TX_, OM_, OM_, DD, OM_, DD, DD, DD};
        int ldo[9] = {TX_, TX_, 1536, 512, 512, 512, 512, 1024, 512};
        int Np[9]  = {TX_, TX_, 512, 512, 512, 512, 512, 512, 512};
        int tr[9]  = {1, 1, 1, 1, 1, 0, 0, 1, 1};
        long offs[9] = {OFF_NAME, OFF_DESC, OFF_FUS1, OFF_OMIC, OFF_IENC2,
                        OFF_W2D, OFF_PRED, OFF_ENC2, OFF_GATE};
        long cum = 0;
        jb.njobs = 9;
        for (int j = 0; j < 9; j++) {
            jb.W[j] = Ws[j]; jb.K[j] = Ks[j]; jb.N[j] = Ns[j];
            jb.ldw[j] = ldw[j]; jb.ldo[j] = ldo[j]; jb.trans[j] = tr[j];
            jb.off[j] = offs[j];
            jb.cum[j] = cum; cum += (long)Np[j] * ldo[j];
        }
        jb.cum[9] = cum;
        cvt_splitW_all<<<(int)((cum + 255) / 256), 256>>>(jb, pWH, pWL);
    }
    cudaEventRecord(evW, 0);

    // ---------------- s3: WFT + WPE + fold_bias ----------------------------
    cudaStreamWaitEvent(s3, evW, 0);
    fold_bias<<<2, DD, 0, s3>>>(pre_b, pre_W, enc_W, pB2);
    hgemm<<<dim3(4, 4), 256, HG_SMEM, s3>>>(pWH + OFF_IENC2, pWL + OFF_IENC2,
        pWH + OFF_W2D, pWL + OFF_W2D,
        nullptr, nullptr, nullptr, nullptr, nullptr, nullptr, pWFH, pWFL,
        512, 512, 16, OM_, 0, 512, 512, 8 | 16);
    hgemm<<<dim3(4, 4), 256, HG_SMEM, s3>>>(pWH + OFF_ENC2, pWL + OFF_ENC2,
        pWH + OFF_PRED, pWL + OFF_PRED,
        nullptr, nullptr, nullptr, nullptr, nullptr, nullptr,
        pWH + OFF_ENC2 + 512, pWL + OFF_ENC2 + 512,
        1024, 512, 16, 512, 0, 1024, 512, 8 | 16);
    cudaEventRecord(ev3, s3);

    // ---------------- s2 (cont.): M_pre = pre_x@WPE + folds ----------------
    cudaStreamWaitEvent(s2, ev3, 0);
    hgemm<<<dim3(4, 128), 256, HG_SMEM, s2>>>(pCHH, pCHL,
        pWH + OFF_ENC2 + 512, pWL + OFF_ENC2 + 512,
        pB2, nullptr, pKO, pB2 + DD,
        nullptr, pMP, nullptr, nullptr,
        512, 1024, 16, DD, 512, 0, 0, 32);
    cudaEventRecord(ev2, s2);

    // ---------------- s1 (cont.): entity GEMM chain ------------------------
    cudaStreamWaitEvent(s1, evW, 0);
    hgemm<<<dim3(6, 8), 256, HG_SMEM, s1>>>(pE1H, pE1L, pWH + OFF_NAME, pWL + OFF_NAME,
        name_b, nullptr, nullptr, nullptr, nullptr, nullptr, pE2H, pE2L,
        TX_, TX_, 24, TX_, 0, 1536, TX_, 1 | 8 | 16);
    hgemm<<<dim3(6, 8), 256, HG_SMEM, s1>>>(pE1H + (size_t)NE_ * TX_, pE1L + (size_t)NE_ * TX_,
        pWH + OFF_DESC, pWL + OFF_DESC,
        desc_b, nullptr, nullptr, nullptr, nullptr, nullptr, pE2H + TX_, pE2L + TX_,
        TX_, TX_, 24, TX_, 0, 1536, TX_, 1 | 8 | 16);
    hgemm<<<dim3(4, 8), 256, HG_SMEM, s1>>>(pE2H, pE2L, pWH + OFF_FUS1, pWL + OFF_FUS1,
        fus_b, nullptr, nullptr, nullptr, nullptr, nullptr, pNDPH, pNDPL,
        1536, 1536, 48, OM_, 0, 512, 512, 8 | 16);
    hgemm<<<dim3(4, 8), 256, HG_SMEM, s1>>>(pNDPH, pNDPL, pWH + OFF_IENC2, pWL + OFF_IENC2,
        nullptr, nullptr, nullptr, nullptr, nullptr, pNDP2, nullptr, nullptr,
        512, 512, 16, DD, 512, 0, 0, 0);
    cudaEventRecord(ev1, s1);

    // ---------------- s0: omic + joined tail -------------------------------
    cudaStreamWaitEvent(0, evX, 0);
    hgemm<<<dim3(4, 128), 256, HG_SMEM>>>(pA1H, pA1L, pWH + OFF_OMIC, pWL + OFF_OMIC,
        omic_b, nullptr, nullptr, nullptr, nullptr, nullptr, pA2H, pA2L,
        512, 512, 16, OM_, 0, 512, 512, 1 | 8 | 16);

    cudaStreamWaitEvent(0, ev1, 0);
    cudaStreamWaitEvent(0, ev3, 0);
    cudaStreamWaitEvent(0, evKO, 0);

    // ienc message (folded): M = omic @ WFT + NDP2[r%1024] + ko⊗ienc_w511
    hgemm<<<dim3(4, 128), 256, HG_SMEM>>>(pA2H, pA2L, pWFH, pWFL,
        nullptr, pNDP2, pKO, ienc_W + (size_t)511 * DD,
        nullptr, pM, nullptr, nullptr,
        512, 512, 16, DD, 512, 0, 0, 4 | 32);

    // gconv(int) -> Zg split into A2
    gconv_int<<<NN, 128>>>(pM, ienc_b, pOFF, pCNT, pSRT, x, pKO, pA2H, pA2L);

    // enc msg: M = Zg @ Wenc + M_pre (K=512; pre half precomputed)
    cudaStreamWaitEvent(0, ev2, 0);
    hgemm<<<dim3(4, 128), 256, HG_SMEM>>>(pA2H, pA2L, pWH + OFF_ENC2, pWL + OFF_ENC2,
        nullptr, nullptr, nullptr, nullptr,
        pMP, pM, nullptr, nullptr,
        512, 1024, 16, DD, 512, 0, 0, 2);

    // gconv(full) at 1024 gathered rows only -> ZK fp32 + split for gate GEMM
    gconv_rows<<<BB * KK, 128>>>(pM, enc_b, pOFF + NN, pCNT + NN, pSRT, bkm,
                                 pZK, pA1H, pA1L);

    // gate GEMM with fused tanh-dot epilogue -> SC (pre-zeroed by set_ko)
    hgemm<<<dim3(4, 8), 256, HG_SMEM>>>(pA1H, pA1L, pWH + OFF_GATE, pWL + OFF_GATE,
        gate_b1, nullptr, nullptr, gate_W2, nullptr, pSC, nullptr, nullptr,
        512, 512, 16, DD, 1, 0, 0, 16 | 64);
    readout2<<<BB, 256>>>(pZK, pSC, gate_b2, reg_W, reg_b, out);

    cudaStreamCaptureStatus cap = cudaStreamCaptureStatusNone;
    cudaStreamIsCapturing(0, &cap);
    if (cap == cudaStreamCaptureStatusNone) {
        cudaStreamDestroy(s1);
        cudaStreamDestroy(s2);
        cudaStreamDestroy(s3);
        cudaEventDestroy(evStart);
        cudaEventDestroy(evW);
        cudaEventDestroy(evX);
        cudaEventDestroy(evKO);
        cudaEventDestroy(ev1);
        cudaEventDestroy(ev2);
        cudaEventDestroy(ev3);
    }

    (void)out_size;
    (void)n_in;
}

// round 12
// speedup vs baseline: 1.1057x; 1.1057x over previous
#include <cuda_runtime.h>
#include <cuda_bf16.h>
#include <cstdint>

#define NN      16384
#define NE_     1024
#define BB      16
#define KK      64
#define TX_     768
#define OM_     511
#define DD      512
#define SLOPE_  0.3f
#define E_INT_MAX 131072
#define E_FULL_MAX 262144

// ------------------------- helpers ------------------------------------------
__device__ __forceinline__ uint32_t smem_to_u32(const void* p) {
    uint32_t a;
    asm("{ .reg .u64 t; cvta.to.shared.u64 t, %1; cvt.u32.u64 %0, t; }"
        : "=r"(a) : "l"(p));
    return a;
}

#define CP_ASYNC16(saddr, gptr) \
    asm volatile("cp.async.cg.shared.global [%0], [%1], 16;" \
                 :: "r"(saddr), "l"(gptr) : "memory")

#define LDMX4(r0, r1, r2, r3, addr) \
    asm volatile("ldmatrix.sync.aligned.m8n8.x4.shared.b16 {%0,%1,%2,%3}, [%4];" \
                 : "=r"(r0), "=r"(r1), "=r"(r2), "=r"(r3) : "r"(addr))

#define MMA16816(c, a, b) \
    asm volatile("mma.sync.aligned.m16n8k16.row.col.f32.bf16.bf16.f32 " \
                 "{%0,%1,%2,%3},{%4,%5,%6,%7},{%8,%9},{%0,%1,%2,%3};" \
                 : "+f"((c)[0]), "+f"((c)[1]), "+f"((c)[2]), "+f"((c)[3]) \
                 : "r"((a)[0]), "r"((a)[1]), "r"((a)[2]), "r"((a)[3]), \
                   "r"((b)[0]), "r"((b)[1]))

// ------------------------- scratch (device globals) -------------------------
__device__ __nv_bfloat16 g_A1H[NN * DD];       // x split; later ZK split
__device__ __nv_bfloat16 g_A1L[NN * DD];
__device__ __nv_bfloat16 g_A2H[NN * DD];       // omic split; later Zg split
__device__ __nv_bfloat16 g_A2L[NN * DD];
__device__ __nv_bfloat16 g_CHH[NN * DD];       // pre_x split
__device__ __nv_bfloat16 g_CHL[NN * DD];
__device__ __nv_bfloat16 g_E1H[2048 * TX_];    // entity emb split (name|desc)
__device__ __nv_bfloat16 g_E1L[2048 * TX_];
__device__ __nv_bfloat16 g_E2H[NE_ * 1536];    // entity linears split
__device__ __nv_bfloat16 g_E2L[NE_ * 1536];
#define WT_TOTAL 3801088
__device__ __nv_bfloat16 g_WH[WT_TOTAL];
__device__ __nv_bfloat16 g_WL[WT_TOTAL];
__device__ __nv_bfloat16 g_WFH[DD * DD];       // WFT split (ienc fold)
__device__ __nv_bfloat16 g_WFL[DD * DD];
__device__ __nv_bfloat16 g_NDPH[NE_ * DD];     // ndpart split
__device__ __nv_bfloat16 g_NDPL[NE_ * DD];
__device__ float g_NDP2[NE_ * DD];             // ndpart @ Wienc'
__device__ float g_B2  [2 * DD];               // [pre_b@Wenc | preW511@Wenc]
__device__ float g_M   [NN * DD];              // message buffer (ienc, then enc)
__device__ float g_MP  [NN * DD];              // M_pre = pre-fold part of enc msg
__device__ float g_ZK  [NE_ * DD];
__device__ float g_H   [NE_ * DD];
__device__ float g_KO  [NN];
__device__ float g_SC  [BB * KK];
__device__ int   g_CNT[2 * NN];
__device__ int   g_OFF[2 * NN];
__device__ int   g_CUR[2 * NN];
__device__ int   g_SRT[E_INT_MAX + E_FULL_MAX];

// ============================================================================
// HMMA split-bf16 GEMM, flag-specialized via template (reduces reg pressure).
// FLAGS: 1 leaky, 2 accumulate (+Cin), 4 add gat[(row&1023)*512+col],
//        8 write split-bf16 (Oh/Ol stride ldo, zero-pad cols [Nc,padN)),
//        16 skip fp32 C write, 32 add koV[row]*w511[col]
// ============================================================================
template <int FLAGS>
__global__ void __launch_bounds__(256, 2)
hgemm(const __nv_bfloat16* __restrict__ Ah, const __nv_bfloat16* __restrict__ Al,
      const __nv_bfloat16* __restrict__ Bh, const __nv_bfloat16* __restrict__ Bl,
      const float* __restrict__ bias, const float* __restrict__ gat,
      const float* __restrict__ koV, const float* __restrict__ w511,
      const float* __restrict__ Cin, float* __restrict__ C,
      __nv_bfloat16* __restrict__ Oh, __nv_bfloat16* __restrict__ Ol,
      int lda_b, int ldb_b, int nchunks, int Nc, int ldc, int ldo,
      int padN)
{
    extern __shared__ char smem[];
    const uint32_t sb = smem_to_u32(smem);
    const int tid  = threadIdx.x;
    const int lane = tid & 31;
    const int wid  = tid >> 5;
    const int wm   = (wid >> 2) * 64;
    const int wn   = (wid & 3) * 32;
    const int bm   = blockIdx.y * 128;
    const int bn   = blockIdx.x * 128;

    float acc[4][4][4];
#pragma unroll
    for (int i = 0; i < 4; i++)
#pragma unroll
        for (int j = 0; j < 4; j++)
#pragma unroll
            for (int q = 0; q < 4; q++) acc[i][j][q] = 0.f;

    auto load_stage = [&](int st, int k0) {
        const uint32_t base = sb + st * 40960;
#pragma unroll
        for (int i = 0; i < 2; i++) {
            const int idx = tid + i * 256;
            const int row = idx >> 2;
            const int c16 = idx & 3;
            const uint32_t so = base + row * 80 + c16 * 16;
            const size_t ga = (size_t)(bm + row) * lda_b + k0 + c16 * 8;
            const size_t gb = (size_t)(bn + row) * ldb_b + k0 + c16 * 8;
            CP_ASYNC16(so,          Ah + ga);
            CP_ASYNC16(so + 10240,  Al + ga);
            CP_ASYNC16(so + 20480,  Bh + gb);
            CP_ASYNC16(so + 30720,  Bl + gb);
        }
        asm volatile("cp.async.commit_group;" ::: "memory");
    };

    auto compute = [&](int st) {
        const uint32_t base = sb + st * 40960;
        const int arow = lane & 15;
        const int asub = (lane >> 4) * 8;
        const int brow = (lane & 7) + (lane >> 4) * 8;
        const int bsub = ((lane >> 3) & 1) * 8;
#pragma unroll
        for (int ks = 0; ks < 2; ks++) {
            const int kb = ks * 16;
            const uint32_t a0 = base + ((wm + arow) * 40 + kb + asub) * 2;
            const uint32_t b0 = base + 20480 + ((wn + brow) * 40 + kb + bsub) * 2;

            uint32_t ah[4][4], bh[4][2];
#pragma unroll
            for (int mt = 0; mt < 4; mt++)
                LDMX4(ah[mt][0], ah[mt][1], ah[mt][2], ah[mt][3], a0 + mt * 16 * 80);
#pragma unroll
            for (int p = 0; p < 2; p++)
                LDMX4(bh[2*p][0], bh[2*p][1], bh[2*p+1][0], bh[2*p+1][1],
                      b0 + p * 16 * 80);
#pragma unroll
            for (int mt = 0; mt < 4; mt++)
#pragma unroll
                for (int nt = 0; nt < 4; nt++)
                    MMA16816(acc[mt][nt], ah[mt], bh[nt]);
#pragma unroll
            for (int p = 0; p < 2; p++) {
                uint32_t bl[2][2];
                LDMX4(bl[0][0], bl[0][1], bl[1][0], bl[1][1],
                      b0 + 10240 + p * 16 * 80);
#pragma unroll
                for (int mt = 0; mt < 4; mt++) {
                    MMA16816(acc[mt][2*p],   ah[mt], bl[0]);
                    MMA16816(acc[mt][2*p+1], ah[mt], bl[1]);
                }
            }
#pragma unroll
            for (int mt = 0; mt < 4; mt++) {
                uint32_t al[4];
                LDMX4(al[0], al[1], al[2], al[3], a0 + 10240 + mt * 16 * 80);
#pragma unroll
                for (int nt = 0; nt < 4; nt++)
                    MMA16816(acc[mt][nt], al, bh[nt]);
            }
        }
    };

    load_stage(0, 0);
    for (int c = 0; c < nchunks; c++) {
        if (c + 1 < nchunks) {
            load_stage((c + 1) & 1, (c + 1) * 32);
            asm volatile("cp.async.wait_group 1;" ::: "memory");
        } else {
            asm volatile("cp.async.wait_group 0;" ::: "memory");
        }
        __syncthreads();
        compute(c & 1);
        __syncthreads();
    }

    // ---- epilogue (specialized; dead paths removed at compile time) ----
    const int er = lane >> 2;
    const int ec = (lane & 3) * 2;
#pragma unroll
    for (int mt = 0; mt < 4; mt++) {
#pragma unroll
        for (int h = 0; h < 2; h++) {
            const int row = bm + wm + mt * 16 + er + h * 8;
            const size_t crow = (size_t)row * ldc;
            const size_t orow = (size_t)row * ldo;
            const size_t grow = (size_t)(row & (NE_ - 1)) * 512;
            const float kv = (FLAGS & 32) ? koV[row] : 0.f;
#pragma unroll
            for (int nt = 0; nt < 4; nt++) {
                const int col = bn + wn + nt * 8 + ec;
                float v0 = acc[mt][nt][h * 2 + 0];
                float v1 = acc[mt][nt][h * 2 + 1];
                if (col + 1 < Nc) {
                    if (bias) {
                        float2 bb = *reinterpret_cast<const float2*>(bias + col);
                        v0 += bb.x; v1 += bb.y;
                    }
                    if (FLAGS & 4) {
                        float2 gg = *reinterpret_cast<const float2*>(gat + grow + col);
                        v0 += gg.x; v1 += gg.y;
                    }
                    if (FLAGS & 32) {
                        float2 ww = *reinterpret_cast<const float2*>(w511 + col);
                        v0 += kv * ww.x; v1 += kv * ww.y;
                    }
                    if (FLAGS & 1) {
                        v0 = v0 > 0.f ? v0 : SLOPE_ * v0;
                        v1 = v1 > 0.f ? v1 : SLOPE_ * v1;
                    }
                    if (FLAGS & 2) {
                        float2 ci = *reinterpret_cast<const float2*>(Cin + crow + col);
                        v0 += ci.x; v1 += ci.y;
                    }
                    if (!(FLAGS & 16))
                        *reinterpret_cast<float2*>(C + crow + col) = make_float2(v0, v1);
                    if (FLAGS & 8) {
                        __nv_bfloat16 h0 = __float2bfloat16(v0);
                        __nv_bfloat16 h1 = __float2bfloat16(v1);
                        __nv_bfloat162 hh; hh.x = h0; hh.y = h1;
                        __nv_bfloat162 ll;
                        ll.x = __float2bfloat16(v0 - __bfloat162float(h0));
                        ll.y = __float2bfloat16(v1 - __bfloat162float(h1));
                        *reinterpret_cast<__nv_bfloat162*>(Oh + orow + col) = hh;
                        *reinterpret_cast<__nv_bfloat162*>(Ol + orow + col) = ll;
                    }
                } else {
                    float vv[2] = {v0, v1};
#pragma unroll
                    for (int q = 0; q < 2; q++) {
                        const int cq = col + q;
                        if (cq < Nc) {
                            float v = vv[q];
                            if (bias)       v += bias[cq];
                            if (FLAGS & 4)  v += gat[grow + cq];
                            if (FLAGS & 32) v += kv * w511[cq];
                            if (FLAGS & 1)  v = v > 0.f ? v : SLOPE_ * v;
                            if (FLAGS & 2)  v += Cin[crow + cq];
                            if (!(FLAGS & 16)) C[crow + cq] = v;
                            if (FLAGS & 8) {
                                __nv_bfloat16 hh = __float2bfloat16(v);
                                Oh[orow + cq] = hh;
                                Ol[orow + cq] = __float2bfloat16(v - __bfloat162float(hh));
                            }
                        } else if ((FLAGS & 8) && cq < padN) {
                            Oh[orow + cq] = __float2bfloat16(0.f);
                            Ol[orow + cq] = __float2bfloat16(0.f);
                        }
                    }
                }
            }
        }
    }
}

// ------------------------- conversion kernels -------------------------------
__global__ void cvt_splitA(const float* __restrict__ A, int M, int K, int lda,
                           int width, int ldrow,
                           __nv_bfloat16* __restrict__ Ah, __nv_bfloat16* __restrict__ Al)
{
    int i = blockIdx.x * blockDim.x + threadIdx.x;
    int half = width >> 1;
    int r = i / half;
    if (r >= M) return;
    int c2 = (i - r * half) * 2;
    float v0 = (c2 < K)     ? A[(size_t)r * lda + c2]     : 0.f;
    float v1 = (c2 + 1 < K) ? A[(size_t)r * lda + c2 + 1] : 0.f;
    __nv_bfloat16 h0 = __float2bfloat16(v0), h1 = __float2bfloat16(v1);
    __nv_bfloat16 l0 = __float2bfloat16(v0 - __bfloat162float(h0));
    __nv_bfloat16 l1 = __float2bfloat16(v1 - __bfloat162float(h1));
    __nv_bfloat162 hh; hh.x = h0; hh.y = h1;
    __nv_bfloat162 ll; ll.x = l0; ll.y = l1;
    *reinterpret_cast<__nv_bfloat162*>(Ah + (size_t)r * ldrow + c2) = hh;
    *reinterpret_cast<__nv_bfloat162*>(Al + (size_t)r * ldrow + c2) = ll;
}

struct WJobs {
    const float* W[9];
    long off[9];
    long cum[10];
    int K[9], N[9], ldw[9], ldo[9], trans[9];
    int njobs;
};

__global__ void cvt_splitW_all(WJobs jobs,
                               __nv_bfloat16* __restrict__ Wh,
                               __nv_bfloat16* __restrict__ Wl)
{
    long gid = (long)blockIdx.x * blockDim.x + threadIdx.x;
    if (gid >= jobs.cum[jobs.njobs]) return;
    int j = 0;
    while (gid >= jobs.cum[j + 1]) j++;
    long local = gid - jobs.cum[j];
    int ldo = jobs.ldo[j];
    int n = (int)(local / ldo);
    int k = (int)(local - (long)n * ldo);
    float v = 0.f;
    if (n < jobs.N[j] && k < jobs.K[j])
        v = jobs.trans[j] ? jobs.W[j][(size_t)k * jobs.ldw[j] + n]
                          : jobs.W[j][(size_t)n * jobs.ldw[j] + k];
    __nv_bfloat16 h = __float2bfloat16(v);
    Wh[jobs.off[j] + local] = h;
    Wl[jobs.off[j] + local] = __float2bfloat16(v - __bfloat162float(h));
}

// B2[0,:] = pre_b @ enc_W ; B2[1,:] = pre_W[511,:] @ enc_W
__global__ void fold_bias(const float* __restrict__ pre_b, const float* __restrict__ pre_W,
                          const float* __restrict__ enc_W, float* __restrict__ B2)
{
    int n = threadIdx.x;
    int which = blockIdx.x;
    const float* v = which ? (pre_W + (size_t)511 * DD) : pre_b;
    float acc = 0.f;
    for (int j = 0; j < DD; j++)
        acc = fmaf(v[j], enc_W[(size_t)j * DD + n], acc);
    B2[which * DD + n] = acc;
}

// ------------------------- misc ----------------------------------------------
__global__ void zero_f(float* __restrict__ p, int n)
{ int i = blockIdx.x * blockDim.x + threadIdx.x; if (i < n) p[i] = 0.f; }
__global__ void zero_i(int* __restrict__ p, int n)
{ int i = blockIdx.x * blockDim.x + threadIdx.x; if (i < n) p[i] = 0; }

__global__ void set_ko(const int* __restrict__ bkm, float* __restrict__ ko)
{
    int i = blockIdx.x * blockDim.x + threadIdx.x;
    if (i < BB * KK) ko[(i >> 6) * NE_ + bkm[i]] = 1.0f;
}

// ------------------------- CSR build -----------------------------------------
__global__ void csr_count2(const int* __restrict__ iei, int Ei,
                           const int* __restrict__ fei, int Ef,
                           int* __restrict__ cnt)
{
    int i = blockIdx.x * blockDim.x + threadIdx.x;
    if (i < Ei) atomicAdd(&cnt[iei[Ei + i]], 1);
    else if (i < Ei + Ef) {
        int j = i - Ei;
        atomicAdd(&cnt[NN + fei[Ef + j]], 1);
    }
}

__global__ void __launch_bounds__(1024, 1)
csr_scan2(const int* __restrict__ cnt, int* __restrict__ off,
          int* __restrict__ cur, int base1)
{
    __shared__ int sa[1024], sbuf[1024];
    const int g = blockIdx.x;
    const int* c = cnt + g * NN;
    int* o = off + g * NN;
    int* u = cur + g * NN;
    int t = threadIdx.x;
    int base = t * 16;
    int loc[16];
    int s = 0;
#pragma unroll
    for (int j = 0; j < 16; j++) { loc[j] = c[base + j]; s += loc[j]; }
    sa[t] = s;
    __syncthreads();
    int* A = sa; int* Bf = sbuf;
    for (int d = 1; d < 1024; d <<= 1) {
        int v = A[t] + (t >= d ? A[t - d] : 0);
        __syncthreads();
        Bf[t] = v;
        __syncthreads();
        int* tmp = A; A = Bf; Bf = tmp;
    }
    int run = (t ? A[t - 1] : 0) + (g ? base1 : 0);
#pragma unroll
    for (int j = 0; j < 16; j++) { o[base + j] = run; u[base + j] = run; run += loc[j]; }
}

__global__ void csr_fill2(const int* __restrict__ iei, int Ei,
                          const int* __restrict__ fei, int Ef,
                          int* __restrict__ cur, int* __restrict__ srt)
{
    int i = blockIdx.x * blockDim.x + threadIdx.x;
    if (i < Ei) {
        int p = atomicAdd(&cur[iei[Ei + i]], 1);
        srt[p] = iei[i];
    } else if (i < Ei + Ef) {
        int j = i - Ei;
        int p = atomicAdd(&cur[NN + fei[Ef + j]], 1);
        srt[p] = fei[j];
    }
}

// gconv(int): Zg = leaky(M[r]+b+sum) + x_c ; emit split bf16 (ld 512)
__global__ void __launch_bounds__(128, 8)
gconv_int(const float* __restrict__ m, const float* __restrict__ bias,
          const int* __restrict__ off, const int* __restrict__ cnt,
          const int* __restrict__ srt,
          const float* __restrict__ x, const float* __restrict__ ko,
          __nv_bfloat16* __restrict__ Oh, __nv_bfloat16* __restrict__ Ol)
{
    const int r = blockIdx.x;
    const int t = threadIdx.x;
    float4 acc = reinterpret_cast<const float4*>(m + (size_t)r * DD)[t];
    float4 b   = reinterpret_cast<const float4*>(bias)[t];
    acc.x += b.x; acc.y += b.y; acc.z += b.z; acc.w += b.w;
    const int s0 = off[r];
    const int d  = cnt[r];
    for (int e = 0; e < d; e++) {
        int s = srt[s0 + e];
        float4 v = reinterpret_cast<const float4*>(m + (size_t)s * DD)[t];
        acc.x += v.x; acc.y += v.y; acc.z += v.z; acc.w += v.w;
    }
    acc.x = acc.x > 0.f ? acc.x : SLOPE_ * acc.x;
    acc.y = acc.y > 0.f ? acc.y : SLOPE_ * acc.y;
    acc.z = acc.z > 0.f ? acc.z : SLOPE_ * acc.z;
    acc.w = acc.w > 0.f ? acc.w : SLOPE_ * acc.w;
    const int c0 = t * 4;
    float vv[4] = {acc.x, acc.y, acc.z, acc.w};
#pragma unroll
    for (int q = 0; q < 4; q++) {
        int c = c0 + q;
        vv[q] += (c < OM_) ? x[(size_t)r * OM_ + c] : ko[r];
    }
    __nv_bfloat16 h[4], l[4];
#pragma unroll
    for (int q = 0; q < 4; q++) {
        h[q] = __float2bfloat16(vv[q]);
        l[q] = __float2bfloat16(vv[q] - __bfloat162float(h[q]));
    }
    size_t o = (size_t)r * DD + c0;
    __nv_bfloat162 h01; h01.x = h[0]; h01.y = h[1];
    __nv_bfloat162 h23; h23.x = h[2]; h23.y = h[3];
    __nv_bfloat162 l01; l01.x = l[0]; l01.y = l[1];
    __nv_bfloat162 l23; l23.x = l[2]; l23.y = l[3];
    *reinterpret_cast<__nv_bfloat162*>(Oh + o)     = h01;
    *reinterpret_cast<__nv_bfloat162*>(Oh + o + 2) = h23;
    *reinterpret_cast<__nv_bfloat162*>(Ol + o)     = l01;
    *reinterpret_cast<__nv_bfloat162*>(Ol + o + 2) = l23;
}

// gconv(full) only at the 1024 gathered KO rows; fused gather_zk
__global__ void __launch_bounds__(128, 8)
gconv_rows(const float* __restrict__ m, const float* __restrict__ bias,
           const int* __restrict__ off, const int* __restrict__ cnt,
           const int* __restrict__ srt, const int* __restrict__ bkm,
           float* __restrict__ ZK,
           __nv_bfloat16* __restrict__ Ah, __nv_bfloat16* __restrict__ Al)
{
    const int i = blockIdx.x;
    const int t = threadIdx.x;
    const int r = bkm[i] + (i >> 6) * NE_;
    float4 acc = reinterpret_cast<const float4*>(m + (size_t)r * DD)[t];
    float4 b   = reinterpret_cast<const float4*>(bias)[t];
    acc.x += b.x; acc.y += b.y; acc.z += b.z; acc.w += b.w;
    const int s0 = off[r];
    const int d  = cnt[r];
    for (int e = 0; e < d; e++) {
        int s = srt[s0 + e];
        float4 v = reinterpret_cast<const float4*>(m + (size_t)s * DD)[t];
        acc.x += v.x; acc.y += v.y; acc.z += v.z; acc.w += v.w;
    }
    acc.x = acc.x > 0.f ? acc.x : SLOPE_ * acc.x;
    acc.y = acc.y > 0.f ? acc.y : SLOPE_ * acc.y;
    acc.z = acc.z > 0.f ? acc.z : SLOPE_ * acc.z;
    acc.w = acc.w > 0.f ? acc.w : SLOPE_ * acc.w;
    reinterpret_cast<float4*>(ZK + (size_t)i * DD)[t] = acc;
    float vv[4] = {acc.x, acc.y, acc.z, acc.w};
    __nv_bfloat16 h[4], l[4];
#pragma unroll
    for (int q = 0; q < 4; q++) {
        h[q] = __float2bfloat16(vv[q]);
        l[q] = __float2bfloat16(vv[q] - __bfloat162float(h[q]));
    }
    size_t o = (size_t)i * DD + t * 4;
    __nv_bfloat162 h01; h01.x = h[0]; h01.y = h[1];
    __nv_bfloat162 h23; h23.x = h[2]; h23.y = h[3];
    __nv_bfloat162 l01; l01.x = l[0]; l01.y = l[1];
    __nv_bfloat162 l23; l23.x = l[2]; l23.y = l[3];
    *reinterpret_cast<__nv_bfloat162*>(Ah + o)     = h01;
    *reinterpret_cast<__nv_bfloat162*>(Ah + o + 2) = h23;
    *reinterpret_cast<__nv_bfloat162*>(Al + o)     = l01;
    *reinterpret_cast<__nv_bfloat162*>(Al + o + 2) = l23;
}

// ------------------------- readout -------------------------------------------
__global__ void tanh_dot(const float* __restrict__ H, const float* __restrict__ W2,
                         const float* __restrict__ b2, float* __restrict__ sc)
{
    int row = blockIdx.x;
    int tid = threadIdx.x;
    __shared__ float red[128];
    float p = 0.f;
    for (int j = tid; j < DD; j += 128)
        p = fmaf(tanhf(H[(size_t)row * DD + j]), W2[j], p);
    red[tid] = p;
    __syncthreads();
    for (int s = 64; s > 0; s >>= 1) {
        if (tid < s) red[tid] += red[tid + s];
        __syncthreads();
    }
    if (tid == 0) sc[row] = red[0] + b2[0];
}

__global__ void readout2(const float* __restrict__ ZK, const float* __restrict__ sc,
                         const float* __restrict__ regW, const float* __restrict__ regb,
                         float* __restrict__ out)
{
    int b = blockIdx.x;
    int tid = threadIdx.x;
    __shared__ float w[KK];
    __shared__ float red[256];
    __shared__ float sm;
    if (tid < KK) w[tid] = sc[b * KK + tid];
    __syncthreads();
    if (tid == 0) {
        float m = w[0];
        for (int k = 1; k < KK; k++) m = fmaxf(m, w[k]);
        float s = 0.f;
        for (int k = 0; k < KK; k++) { w[k] = expf(w[k] - m); s += w[k]; }
        sm = s;
    }
    __syncthreads();
    int c0 = tid, c1 = tid + 256;
    float r0 = 0.f, r1 = 0.f;
    for (int k = 0; k < KK; k++) {
        const float* z = ZK + ((size_t)b * KK + k) * DD;
        float wk = w[k];
        r0 = fmaf(wk, z[c0], r0);
        r1 = fmaf(wk, z[c1], r1);
    }
    float part = (r0 * regW[c0] + r1 * regW[c1]) / sm;
    red[tid] = part;
    __syncthreads();
    for (int s = 128; s > 0; s >>= 1) {
        if (tid < s) red[tid] += red[tid + s];
        __syncthreads();
    }
    if (tid == 0) out[b] = red[0] + regb[0];
}

// ------------------------- host side ------------------------------------------
static const int HG_SMEM = 2 * 40960;

extern "C" void kernel_launch(void* const* d_in, const int* in_sizes, int n_in,
                              void* d_out, int out_size)
{
    int map_[31];
    {
        int p = 0;
        for (int l = 0; l < 31; l++) {
            if (l == 5 || l == 8) {
                bool present = (n_in == 31);
                if (present && p < n_in && in_sizes[p] == 1) map_[l] = p++;
                else map_[l] = -1;
            } else map_[l] = p++;
        }
    }
    auto F = [&](int l) -> const float* { return (const float*)d_in[map_[l]]; };
    auto I = [&](int l) -> const int*   { return (const int*)d_in[map_[l]]; };

    const float* x        = F(0);
    const float* pre_x    = F(1);
    const int*   edge_ei  = I(2);
    const int*   int_ei   = I(3);
    const float* name_emb = F(6);
    const float* desc_emb = F(7);
    const int*   bkm      = I(9);
    const float* name_W = F(11), *name_b = F(12);
    const float* desc_W = F(13), *desc_b = F(14);
    const float* omic_W = F(15), *omic_b = F(16);
    const float* fus_W  = F(17), *fus_b  = F(18);
    const float* pre_W  = F(19), *pre_b  = F(20);
    const float* ienc_W = F(21), *ienc_b = F(22);
    const float* enc_W  = F(23), *enc_b  = F(24);
    const float* gate_W1 = F(25), *gate_b1 = F(26);
    const float* gate_W2 = F(27), *gate_b2 = F(28);
    const float* reg_W   = F(29), *reg_b   = F(30);
    float* out = (float*)d_out;

    const int E_full = in_sizes[map_[2]] / 2;
    const int E_int  = in_sizes[map_[3]] / 2;
    const float* W2 = fus_W + (size_t)1536 * OM_;

    __nv_bfloat16 *pA1H, *pA1L, *pA2H, *pA2L, *pCHH, *pCHL, *pE1H, *pE1L, *pE2H, *pE2L;
    __nv_bfloat16 *pWH, *pWL, *pWFH, *pWFL, *pNDPH, *pNDPL;
    float *pNDP2, *pB2, *pM, *pMP, *pZK, *pH, *pKO, *pSC;
    int *pCNT, *pOFF, *pCUR, *pSRT;
    cudaGetSymbolAddress((void**)&pA1H, g_A1H);
    cudaGetSymbolAddress((void**)&pA1L, g_A1L);
    cudaGetSymbolAddress((void**)&pA2H, g_A2H);
    cudaGetSymbolAddress((void**)&pA2L, g_A2L);
    cudaGetSymbolAddress((void**)&pCHH, g_CHH);
    cudaGetSymbolAddress((void**)&pCHL, g_CHL);
    cudaGetSymbolAddress((void**)&pE1H, g_E1H);
    cudaGetSymbolAddress((void**)&pE1L, g_E1L);
    cudaGetSymbolAddress((void**)&pE2H, g_E2H);
    cudaGetSymbolAddress((void**)&pE2L, g_E2L);
    cudaGetSymbolAddress((void**)&pWH,  g_WH);
    cudaGetSymbolAddress((void**)&pWL,  g_WL);
    cudaGetSymbolAddress((void**)&pWFH, g_WFH);
    cudaGetSymbolAddress((void**)&pWFL, g_WFL);
    cudaGetSymbolAddress((void**)&pNDPH, g_NDPH);
    cudaGetSymbolAddress((void**)&pNDPL, g_NDPL);
    cudaGetSymbolAddress((void**)&pNDP2, g_NDP2);
    cudaGetSymbolAddress((void**)&pB2,  g_B2);
    cudaGetSymbolAddress((void**)&pM,   g_M);
    cudaGetSymbolAddress((void**)&pMP,  g_MP);
    cudaGetSymbolAddress((void**)&pZK,  g_ZK);
    cudaGetSymbolAddress((void**)&pH,   g_H);
    cudaGetSymbolAddress((void**)&pKO,  g_KO);
    cudaGetSymbolAddress((void**)&pSC,  g_SC);
    cudaGetSymbolAddress((void**)&pCNT, g_CNT);
    cudaGetSymbolAddress((void**)&pOFF, g_OFF);
    cudaGetSymbolAddress((void**)&pCUR, g_CUR);
    cudaGetSymbolAddress((void**)&pSRT, g_SRT);

    cudaFuncSetAttribute(hgemm<0>,          cudaFuncAttributeMaxDynamicSharedMemorySize, HG_SMEM);
    cudaFuncSetAttribute(hgemm<2>,          cudaFuncAttributeMaxDynamicSharedMemorySize, HG_SMEM);
    cudaFuncSetAttribute(hgemm<32>,         cudaFuncAttributeMaxDynamicSharedMemorySize, HG_SMEM);
    cudaFuncSetAttribute(hgemm<4 | 32>,     cudaFuncAttributeMaxDynamicSharedMemorySize, HG_SMEM);
    cudaFuncSetAttribute(hgemm<8 | 16>,     cudaFuncAttributeMaxDynamicSharedMemorySize, HG_SMEM);
    cudaFuncSetAttribute(hgemm<1 | 8 | 16>, cudaFuncAttributeMaxDynamicSharedMemorySize, HG_SMEM);

    const long OFF_NAME  = 0;        // 768x768  name^T
    const long OFF_DESC  = 589824;   // 768x768  desc^T
    const long OFF_FUS1  = 1179648;  // 512x1536 fus[0:1536]^T
    const long OFF_OMIC  = 1966080;  // 512x512  omic^T
    const long OFF_IENC2 = 2228224;  // 512x512  ienc'^T
    const long OFF_W2D   = 2490368;  // 512x512  fus2 direct
    const long OFF_PRED  = 2752512;  // 512x512  pre_W direct
    const long OFF_ENC2  = 3014656;  // 512x1024 [enc^T | WPE^T]
    const long OFF_GATE  = 3538944;  // 512x512  gate1^T

    cudaStream_t s1, s2, s3;
    cudaStreamCreateWithFlags(&s1, cudaStreamNonBlocking);
    cudaStreamCreateWithFlags(&s2, cudaStreamNonBlocking);
    cudaStreamCreateWithFlags(&s3, cudaStreamNonBlocking);
    cudaEvent_t evStart, evW, evX, evKO, ev1, ev2, ev3;
    cudaEventCreateWithFlags(&evStart, cudaEventDisableTiming);
    cudaEventCreateWithFlags(&evW,     cudaEventDisableTiming);
    cudaEventCreateWithFlags(&evX,     cudaEventDisableTiming);
    cudaEventCreateWithFlags(&evKO,    cudaEventDisableTiming);
    cudaEventCreateWithFlags(&ev1,     cudaEventDisableTiming);
    cudaEventCreateWithFlags(&ev2,     cudaEventDisableTiming);
    cudaEventCreateWithFlags(&ev3,     cudaEventDisableTiming);

    cudaEventRecord(evStart, 0);
    cudaStreamWaitEvent(s1, evStart, 0);
    cudaStreamWaitEvent(s2, evStart, 0);

    // ---------------- s2: x split | KO | CSR | pre split | M_pre -----------
    cvt_splitA<<<(NN * 256 + 255) / 256, 256, 0, s2>>>(x, NN, OM_, OM_, 512, 512, pA1H, pA1L);
    cudaEventRecord(evX, s2);
    zero_f<<<(NN + 255) / 256, 256, 0, s2>>>(pKO, NN);
    set_ko<<<(BB * KK + 255) / 256, 256, 0, s2>>>(bkm, pKO);
    zero_i<<<(2 * NN + 255) / 256, 256, 0, s2>>>(pCNT, 2 * NN);
    csr_count2<<<(E_int + E_full + 255) / 256, 256, 0, s2>>>(int_ei, E_int, edge_ei, E_full, pCNT);
    csr_scan2<<<2, 1024, 0, s2>>>(pCNT, pOFF, pCUR, E_int);
    csr_fill2<<<(E_int + E_full + 255) / 256, 256, 0, s2>>>(int_ei, E_int, edge_ei, E_full, pCUR, pSRT);
    cudaEventRecord(evKO, s2);
    cvt_splitA<<<(NN * 256 + 255) / 256, 256, 0, s2>>>(pre_x, NN, OM_, OM_, 512, 512, pCHH, pCHL);

    // ---------------- s1: entity emb conversions (no weight dep) ----------
    cvt_splitA<<<(NE_ * 384 + 255) / 256, 256, 0, s1>>>(name_emb, NE_, TX_, TX_, TX_, TX_, pE1H, pE1L);
    cvt_splitA<<<(NE_ * 384 + 255) / 256, 256, 0, s1>>>(desc_emb, NE_, TX_, TX_, TX_, TX_,
                                                        pE1H + (size_t)NE_ * TX_,
                                                        pE1L + (size_t)NE_ * TX_);

    // ---------------- s0: weight conversion -------------------------------
    {
        WJobs jb;
        const float* Ws[9] = {name_W, desc_W, fus_W, omic_W, ienc_W, W2, pre_W, enc_W, gate_W1};
        int Ks[9]  = {TX_, TX_, 1536, OM_, OM_, OM_, DD, DD, DD};
        int Ns[9]  = {TX_, TX_, OM_, OM_, DD, OM_, DD, DD, DD};
        int ldw[9] = {TX_, TX_, OM_, OM_, DD, OM_, DD, DD, DD};
        int ldo[9] = {TX_, TX_, 1536, 512, 512, 512, 512, 1024, 512};
        int Np[9]  = {TX_, TX_, 512, 512, 512, 512, 512, 512, 512};
        int tr[9]  = {1, 1, 1, 1, 1, 0, 0, 1, 1};
        long offs[9] = {OFF_NAME, OFF_DESC, OFF_FUS1, OFF_OMIC, OFF_IENC2,
                        OFF_W2D, OFF_PRED, OFF_ENC2, OFF_GATE};
        long cum = 0;
        jb.njobs = 9;
        for (int j = 0; j < 9; j++) {
            jb.W[j] = Ws[j]; jb.K[j] = Ks[j]; jb.N[j] = Ns[j];
            jb.ldw[j] = ldw[j]; jb.ldo[j] = ldo[j]; jb.trans[j] = tr[j];
            jb.off[j] = offs[j];
            jb.cum[j] = cum; cum += (long)Np[j] * ldo[j];
        }
        jb.cum[9] = cum;
        cvt_splitW_all<<<(int)((cum + 255) / 256), 256>>>(jb, pWH, pWL);
    }
    cudaEventRecord(evW, 0);

    // ---------------- s3: WFT + WPE + fold_bias ----------------------------
    cudaStreamWaitEvent(s3, evW, 0);
    fold_bias<<<2, DD, 0, s3>>>(pre_b, pre_W, enc_W, pB2);
    hgemm<8 | 16><<<dim3(4, 4), 256, HG_SMEM, s3>>>(pWH + OFF_IENC2, pWL + OFF_IENC2,
        pWH + OFF_W2D, pWL + OFF_W2D,
        nullptr, nullptr, nullptr, nullptr, nullptr, nullptr, pWFH, pWFL,
        512, 512, 16, OM_, 0, 512, 512);
    hgemm<8 | 16><<<dim3(4, 4), 256, HG_SMEM, s3>>>(pWH + OFF_ENC2, pWL + OFF_ENC2,
        pWH + OFF_PRED, pWL + OFF_PRED,
        nullptr, nullptr, nullptr, nullptr, nullptr, nullptr,
        pWH + OFF_ENC2 + 512, pWL + OFF_ENC2 + 512,
        1024, 512, 16, 512, 0, 1024, 512);
    cudaEventRecord(ev3, s3);

    // ---------------- s2 (cont.): M_pre = pre_x@WPE + folds ----------------
    cudaStreamWaitEvent(s2, ev3, 0);
    hgemm<32><<<dim3(4, 128), 256, HG_SMEM, s2>>>(pCHH, pCHL,
        pWH + OFF_ENC2 + 512, pWL + OFF_ENC2 + 512,
        pB2, nullptr, pKO, pB2 + DD,
        nullptr, pMP, nullptr, nullptr,
        512, 1024, 16, DD, 512, 0, 0);
    cudaEventRecord(ev2, s2);

    // ---------------- s1 (cont.): entity GEMM chain ------------------------
    cudaStreamWaitEvent(s1, evW, 0);
    hgemm<1 | 8 | 16><<<dim3(6, 8), 256, HG_SMEM, s1>>>(pE1H, pE1L,
        pWH + OFF_NAME, pWL + OFF_NAME,
        name_b, nullptr, nullptr, nullptr, nullptr, nullptr, pE2H, pE2L,
        TX_, TX_, 24, TX_, 0, 1536, TX_);
    hgemm<1 | 8 | 16><<<dim3(6, 8), 256, HG_SMEM, s1>>>(pE1H + (size_t)NE_ * TX_,
        pE1L + (size_t)NE_ * TX_,
        pWH + OFF_DESC, pWL + OFF_DESC,
        desc_b, nullptr, nullptr, nullptr, nullptr, nullptr, pE2H + TX_, pE2L + TX_,
        TX_, TX_, 24, TX_, 0, 1536, TX_);
    hgemm<8 | 16><<<dim3(4, 8), 256, HG_SMEM, s1>>>(pE2H, pE2L,
        pWH + OFF_FUS1, pWL + OFF_FUS1,
        fus_b, nullptr, nullptr, nullptr, nullptr, nullptr, pNDPH, pNDPL,
        1536, 1536, 48, OM_, 0, 512, 512);
    hgemm<0><<<dim3(4, 8), 256, HG_SMEM, s1>>>(pNDPH, pNDPL,
        pWH + OFF_IENC2, pWL + OFF_IENC2,
        nullptr, nullptr, nullptr, nullptr, nullptr, pNDP2, nullptr, nullptr,
        512, 512, 16, DD, 512, 0, 0);
    cudaEventRecord(ev1, s1);

    // ---------------- s0: omic + joined tail -------------------------------
    cudaStreamWaitEvent(0, evX, 0);
    hgemm<1 | 8 | 16><<<dim3(4, 128), 256, HG_SMEM>>>(pA1H, pA1L,
        pWH + OFF_OMIC, pWL + OFF_OMIC,
        omic_b, nullptr, nullptr, nullptr, nullptr, nullptr, pA2H, pA2L,
        512, 512, 16, OM_, 0, 512, 512);

    cudaStreamWaitEvent(0, ev1, 0);
    cudaStreamWaitEvent(0, ev3, 0);
    cudaStreamWaitEvent(0, evKO, 0);

    // ienc message (folded): M = omic @ WFT + NDP2[r%1024] + ko⊗ienc_w511
    hgemm<4 | 32><<<dim3(4, 128), 256, HG_SMEM>>>(pA2H, pA2L, pWFH, pWFL,
        nullptr, pNDP2, pKO, ienc_W + (size_t)511 * DD,
        nullptr, pM, nullptr, nullptr,
        512, 512, 16, DD, 512, 0, 0);

    // gconv(int) -> Zg split into A2
    gconv_int<<<NN, 128>>>(pM, ienc_b, pOFF, pCNT, pSRT, x, pKO, pA2H, pA2L);

    // enc msg: M = Zg @ Wenc + M_pre (K=512; pre half precomputed)
    cudaStreamWaitEvent(0, ev2, 0);
    hgemm<2><<<dim3(4, 128), 256, HG_SMEM>>>(pA2H, pA2L,
        pWH + OFF_ENC2, pWL + OFF_ENC2,
        nullptr, nullptr, nullptr, nullptr,
        pMP, pM, nullptr, nullptr,
        512, 1024, 16, DD, 512, 0, 0);

    // gconv(full) at 1024 gathered rows only -> ZK fp32 + split for gate GEMM
    gconv_rows<<<BB * KK, 128>>>(pM, enc_b, pOFF + NN, pCNT + NN, pSRT, bkm,
                                 pZK, pA1H, pA1L);

    // gate GEMM + gated readout
    hgemm<0><<<dim3(4, 8), 256, HG_SMEM>>>(pA1H, pA1L,
        pWH + OFF_GATE, pWL + OFF_GATE,
        gate_b1, nullptr, nullptr, nullptr, nullptr, pH, nullptr, nullptr,
        512, 512, 16, DD, 512, 0, 0);
    tanh_dot<<<BB * KK, 128>>>(pH, gate_W2, gate_b2, pSC);
    readout2<<<BB, 256>>>(pZK, pSC, reg_W, reg_b, out);

    cudaStreamCaptureStatus cap = cudaStreamCaptureStatusNone;
    cudaStreamIsCapturing(0, &cap);
    if (cap == cudaStreamCaptureStatusNone) {
        cudaStreamDestroy(s1);
        cudaStreamDestroy(s2);
        cudaStreamDestroy(s3);
        cudaEventDestroy(evStart);
        cudaEventDestroy(evW);
        cudaEventDestroy(evX);
        cudaEventDestroy(evKO);
        cudaEventDestroy(ev1);
        cudaEventDestroy(ev2);
        cudaEventDestroy(ev3);
    }

    (void)out_size;
    (void)n_in;
}

// round 13
// speedup vs baseline: 1.1361x; 1.0275x over previous
#include <cuda_runtime.h>
#include <cuda_bf16.h>
#include <cstdint>

#define NN      16384
#define NE_     1024
#define BB      16
#define KK      64
#define TX_     768
#define OM_     511
#define DD      512
#define SLOPE_  0.3f
#define E_INT_MAX 131072
#define E_FULL_MAX 262144
#define HALF_M  8192

// ------------------------- helpers ------------------------------------------
__device__ __forceinline__ uint32_t smem_to_u32(const void* p) {
    uint32_t a;
    asm("{ .reg .u64 t; cvta.to.shared.u64 t, %1; cvt.u32.u64 %0, t; }"
        : "=r"(a) : "l"(p));
    return a;
}

#define CP_ASYNC16(saddr, gptr) \
    asm volatile("cp.async.cg.shared.global [%0], [%1], 16;" \
                 :: "r"(saddr), "l"(gptr) : "memory")

#define LDMX4(r0, r1, r2, r3, addr) \
    asm volatile("ldmatrix.sync.aligned.m8n8.x4.shared.b16 {%0,%1,%2,%3}, [%4];" \
                 : "=r"(r0), "=r"(r1), "=r"(r2), "=r"(r3) : "r"(addr))

#define MMA16816(c, a, b) \
    asm volatile("mma.sync.aligned.m16n8k16.row.col.f32.bf16.bf16.f32 " \
                 "{%0,%1,%2,%3},{%4,%5,%6,%7},{%8,%9},{%0,%1,%2,%3};" \
                 : "+f"((c)[0]), "+f"((c)[1]), "+f"((c)[2]), "+f"((c)[3]) \
                 : "r"((a)[0]), "r"((a)[1]), "r"((a)[2]), "r"((a)[3]), \
                   "r"((b)[0]), "r"((b)[1]))

// ------------------------- scratch (device globals) -------------------------
__device__ __nv_bfloat16 g_A1H[NN * DD];       // x split; later ZK split
__device__ __nv_bfloat16 g_A1L[NN * DD];
__device__ __nv_bfloat16 g_A2H[NN * DD];       // omic split; later Zg split
__device__ __nv_bfloat16 g_A2L[NN * DD];
__device__ __nv_bfloat16 g_CHH[NN * DD];       // pre_x split
__device__ __nv_bfloat16 g_CHL[NN * DD];
__device__ __nv_bfloat16 g_E1H[2048 * TX_];    // entity emb split (name|desc)
__device__ __nv_bfloat16 g_E1L[2048 * TX_];
__device__ __nv_bfloat16 g_E2H[NE_ * 1536];    // entity linears split
__device__ __nv_bfloat16 g_E2L[NE_ * 1536];
#define WT_TOTAL 3801088
__device__ __nv_bfloat16 g_WH[WT_TOTAL];
__device__ __nv_bfloat16 g_WL[WT_TOTAL];
__device__ __nv_bfloat16 g_WFH[DD * DD];       // WFT split (ienc fold)
__device__ __nv_bfloat16 g_WFL[DD * DD];
__device__ __nv_bfloat16 g_NDPH[NE_ * DD];     // ndpart split
__device__ __nv_bfloat16 g_NDPL[NE_ * DD];
__device__ float g_NDP2[NE_ * DD];             // ndpart @ Wienc'
__device__ float g_B2  [2 * DD];               // [pre_b@Wenc | preW511@Wenc]
__device__ float g_M   [NN * DD];              // message buffer (ienc, then enc)
__device__ float g_MP  [NN * DD];              // M_pre = pre-fold part of enc msg
__device__ float g_ZK  [NE_ * DD];
__device__ float g_H   [NE_ * DD];
__device__ float g_KO  [NN];
__device__ float g_SC  [BB * KK];
__device__ int   g_CNT[2 * NN];
__device__ int   g_OFF[2 * NN];
__device__ int   g_CUR[2 * NN];
__device__ int   g_SRT[E_INT_MAX + E_FULL_MAX];

// ============================================================================
// HMMA split-bf16 GEMM, flag-specialized, one-sync pipelined mainloop.
// FLAGS: 1 leaky, 2 accumulate (+Cin), 4 add gat[(row&1023)*512+col],
//        8 write split-bf16 (Oh/Ol stride ldo, zero-pad cols [Nc,padN)),
//        16 skip fp32 C write, 32 add koV[row]*w511[col]
// ============================================================================
template <int FLAGS>
__global__ void __launch_bounds__(256, 2)
hgemm(const __nv_bfloat16* __restrict__ Ah, const __nv_bfloat16* __restrict__ Al,
      const __nv_bfloat16* __restrict__ Bh, const __nv_bfloat16* __restrict__ Bl,
      const float* __restrict__ bias, const float* __restrict__ gat,
      const float* __restrict__ koV, const float* __restrict__ w511,
      const float* __restrict__ Cin, float* __restrict__ C,
      __nv_bfloat16* __restrict__ Oh, __nv_bfloat16* __restrict__ Ol,
      int lda_b, int ldb_b, int nchunks, int Nc, int ldc, int ldo,
      int padN)
{
    extern __shared__ char smem[];
    const uint32_t sb = smem_to_u32(smem);
    const int tid  = threadIdx.x;
    const int lane = tid & 31;
    const int wid  = tid >> 5;
    const int wm   = (wid >> 2) * 64;
    const int wn   = (wid & 3) * 32;
    const int bm   = blockIdx.y * 128;
    const int bn   = blockIdx.x * 128;

    float acc[4][4][4];
#pragma unroll
    for (int i = 0; i < 4; i++)
#pragma unroll
        for (int j = 0; j < 4; j++)
#pragma unroll
            for (int q = 0; q < 4; q++) acc[i][j][q] = 0.f;

    auto load_stage = [&](int st, int k0) {
        const uint32_t base = sb + st * 40960;
#pragma unroll
        for (int i = 0; i < 2; i++) {
            const int idx = tid + i * 256;
            const int row = idx >> 2;
            const int c16 = idx & 3;
            const uint32_t so = base + row * 80 + c16 * 16;
            const size_t ga = (size_t)(bm + row) * lda_b + k0 + c16 * 8;
            const size_t gb = (size_t)(bn + row) * ldb_b + k0 + c16 * 8;
            CP_ASYNC16(so,          Ah + ga);
            CP_ASYNC16(so + 10240,  Al + ga);
            CP_ASYNC16(so + 20480,  Bh + gb);
            CP_ASYNC16(so + 30720,  Bl + gb);
        }
        asm volatile("cp.async.commit_group;" ::: "memory");
    };

    auto compute = [&](int st) {
        const uint32_t base = sb + st * 40960;
        const int arow = lane & 15;
        const int asub = (lane >> 4) * 8;
        const int brow = (lane & 7) + (lane >> 4) * 8;
        const int bsub = ((lane >> 3) & 1) * 8;
#pragma unroll
        for (int ks = 0; ks < 2; ks++) {
            const int kb = ks * 16;
            const uint32_t a0 = base + ((wm + arow) * 40 + kb + asub) * 2;
            const uint32_t b0 = base + 20480 + ((wn + brow) * 40 + kb + bsub) * 2;

            uint32_t ah[4][4], bh[4][2];
#pragma unroll
            for (int mt = 0; mt < 4; mt++)
                LDMX4(ah[mt][0], ah[mt][1], ah[mt][2], ah[mt][3], a0 + mt * 16 * 80);
#pragma unroll
            for (int p = 0; p < 2; p++)
                LDMX4(bh[2*p][0], bh[2*p][1], bh[2*p+1][0], bh[2*p+1][1],
                      b0 + p * 16 * 80);
#pragma unroll
            for (int mt = 0; mt < 4; mt++)
#pragma unroll
                for (int nt = 0; nt < 4; nt++)
                    MMA16816(acc[mt][nt], ah[mt], bh[nt]);
#pragma unroll
            for (int p = 0; p < 2; p++) {
                uint32_t bl[2][2];
                LDMX4(bl[0][0], bl[0][1], bl[1][0], bl[1][1],
                      b0 + 10240 + p * 16 * 80);
#pragma unroll
                for (int mt = 0; mt < 4; mt++) {
                    MMA16816(acc[mt][2*p],   ah[mt], bl[0]);
                    MMA16816(acc[mt][2*p+1], ah[mt], bl[1]);
                }
            }
#pragma unroll
            for (int mt = 0; mt < 4; mt++) {
                uint32_t al[4];
                LDMX4(al[0], al[1], al[2], al[3], a0 + 10240 + mt * 16 * 80);
#pragma unroll
                for (int nt = 0; nt < 4; nt++)
                    MMA16816(acc[mt][nt], al, bh[nt]);
            }
        }
    };

    // one-sync pipelined mainloop: the barrier both publishes chunk c's loads
    // and retires compute(c-1)'s reads of buffer (c+1)&1.
    load_stage(0, 0);
    for (int c = 0; c < nchunks; c++) {
        asm volatile("cp.async.wait_group 0;" ::: "memory");
        __syncthreads();
        if (c + 1 < nchunks) load_stage((c + 1) & 1, (c + 1) * 32);
        compute(c & 1);
    }

    // ---- epilogue (specialized; dead paths removed at compile time) ----
    const int er = lane >> 2;
    const int ec = (lane & 3) * 2;
#pragma unroll
    for (int mt = 0; mt < 4; mt++) {
#pragma unroll
        for (int h = 0; h < 2; h++) {
            const int row = bm + wm + mt * 16 + er + h * 8;
            const size_t crow = (size_t)row * ldc;
            const size_t orow = (size_t)row * ldo;
            const size_t grow = (size_t)(row & (NE_ - 1)) * 512;
            const float kv = (FLAGS & 32) ? koV[row] : 0.f;
#pragma unroll
            for (int nt = 0; nt < 4; nt++) {
                const int col = bn + wn + nt * 8 + ec;
                float v0 = acc[mt][nt][h * 2 + 0];
                float v1 = acc[mt][nt][h * 2 + 1];
                if (col + 1 < Nc) {
                    if (bias) {
                        float2 bb = *reinterpret_cast<const float2*>(bias + col);
                        v0 += bb.x; v1 += bb.y;
                    }
                    if (FLAGS & 4) {
                        float2 gg = *reinterpret_cast<const float2*>(gat + grow + col);
                        v0 += gg.x; v1 += gg.y;
                    }
                    if (FLAGS & 32) {
                        float2 ww = *reinterpret_cast<const float2*>(w511 + col);
                        v0 += kv * ww.x; v1 += kv * ww.y;
                    }
                    if (FLAGS & 1) {
                        v0 = v0 > 0.f ? v0 : SLOPE_ * v0;
                        v1 = v1 > 0.f ? v1 : SLOPE_ * v1;
                    }
                    if (FLAGS & 2) {
                        float2 ci = *reinterpret_cast<const float2*>(Cin + crow + col);
                        v0 += ci.x; v1 += ci.y;
                    }
                    if (!(FLAGS & 16))
                        *reinterpret_cast<float2*>(C + crow + col) = make_float2(v0, v1);
                    if (FLAGS & 8) {
                        __nv_bfloat16 h0 = __float2bfloat16(v0);
                        __nv_bfloat16 h1 = __float2bfloat16(v1);
                        __nv_bfloat162 hh; hh.x = h0; hh.y = h1;
                        __nv_bfloat162 ll;
                        ll.x = __float2bfloat16(v0 - __bfloat162float(h0));
                        ll.y = __float2bfloat16(v1 - __bfloat162float(h1));
                        *reinterpret_cast<__nv_bfloat162*>(Oh + orow + col) = hh;
                        *reinterpret_cast<__nv_bfloat162*>(Ol + orow + col) = ll;
                    }
                } else {
                    float vv[2] = {v0, v1};
#pragma unroll
                    for (int q = 0; q < 2; q++) {
                        const int cq = col + q;
                        if (cq < Nc) {
                            float v = vv[q];
                            if (bias)       v += bias[cq];
                            if (FLAGS & 4)  v += gat[grow + cq];
                            if (FLAGS & 32) v += kv * w511[cq];
                            if (FLAGS & 1)  v = v > 0.f ? v : SLOPE_ * v;
                            if (FLAGS & 2)  v += Cin[crow + cq];
                            if (!(FLAGS & 16)) C[crow + cq] = v;
                            if (FLAGS & 8) {
                                __nv_bfloat16 hh = __float2bfloat16(v);
                                Oh[orow + cq] = hh;
                                Ol[orow + cq] = __float2bfloat16(v - __bfloat162float(hh));
                            }
                        } else if ((FLAGS & 8) && cq < padN) {
                            Oh[orow + cq] = __float2bfloat16(0.f);
                            Ol[orow + cq] = __float2bfloat16(0.f);
                        }
                    }
                }
            }
        }
    }
}

// ------------------------- conversion kernels -------------------------------
__global__ void cvt_splitA(const float* __restrict__ A, int M, int K, int lda,
                           int width, int ldrow,
                           __nv_bfloat16* __restrict__ Ah, __nv_bfloat16* __restrict__ Al)
{
    int i = blockIdx.x * blockDim.x + threadIdx.x;
    int half = width >> 1;
    int r = i / half;
    if (r >= M) return;
    int c2 = (i - r * half) * 2;
    float v0 = (c2 < K)     ? A[(size_t)r * lda + c2]     : 0.f;
    float v1 = (c2 + 1 < K) ? A[(size_t)r * lda + c2 + 1] : 0.f;
    __nv_bfloat16 h0 = __float2bfloat16(v0), h1 = __float2bfloat16(v1);
    __nv_bfloat16 l0 = __float2bfloat16(v0 - __bfloat162float(h0));
    __nv_bfloat16 l1 = __float2bfloat16(v1 - __bfloat162float(h1));
    __nv_bfloat162 hh; hh.x = h0; hh.y = h1;
    __nv_bfloat162 ll; ll.x = l0; ll.y = l1;
    *reinterpret_cast<__nv_bfloat162*>(Ah + (size_t)r * ldrow + c2) = hh;
    *reinterpret_cast<__nv_bfloat162*>(Al + (size_t)r * ldrow + c2) = ll;
}

struct WJobs {
    const float* W[9];
    long off[9];
    long cum[10];
    int K[9], N[9], ldw[9], ldo[9], trans[9];
    int njobs;
};

__global__ void cvt_splitW_all(WJobs jobs,
                               __nv_bfloat16* __restrict__ Wh,
                               __nv_bfloat16* __restrict__ Wl)
{
    long gid = (long)blockIdx.x * blockDim.x + threadIdx.x;
    if (gid >= jobs.cum[jobs.njobs]) return;
    int j = 0;
    while (gid >= jobs.cum[j + 1]) j++;
    long local = gid - jobs.cum[j];
    int ldo = jobs.ldo[j];
    int n = (int)(local / ldo);
    int k = (int)(local - (long)n * ldo);
    float v = 0.f;
    if (n < jobs.N[j] && k < jobs.K[j])
        v = jobs.trans[j] ? jobs.W[j][(size_t)k * jobs.ldw[j] + n]
                          : jobs.W[j][(size_t)n * jobs.ldw[j] + k];
    __nv_bfloat16 h = __float2bfloat16(v);
    Wh[jobs.off[j] + local] = h;
    Wl[jobs.off[j] + local] = __float2bfloat16(v - __bfloat162float(h));
}

// B2[0,:] = pre_b @ enc_W ; B2[1,:] = pre_W[511,:] @ enc_W
__global__ void fold_bias(const float* __restrict__ pre_b, const float* __restrict__ pre_W,
                          const float* __restrict__ enc_W, float* __restrict__ B2)
{
    int n = threadIdx.x;
    int which = blockIdx.x;
    const float* v = which ? (pre_W + (size_t)511 * DD) : pre_b;
    float acc = 0.f;
    for (int j = 0; j < DD; j++)
        acc = fmaf(v[j], enc_W[(size_t)j * DD + n], acc);
    B2[which * DD + n] = acc;
}

// ------------------------- misc ----------------------------------------------
__global__ void zero_f(float* __restrict__ p, int n)
{ int i = blockIdx.x * blockDim.x + threadIdx.x; if (i < n) p[i] = 0.f; }
__global__ void zero_i(int* __restrict__ p, int n)
{ int i = blockIdx.x * blockDim.x + threadIdx.x; if (i < n) p[i] = 0; }

__global__ void set_ko(const int* __restrict__ bkm, float* __restrict__ ko)
{
    int i = blockIdx.x * blockDim.x + threadIdx.x;
    if (i < BB * KK) ko[(i >> 6) * NE_ + bkm[i]] = 1.0f;
}

// ------------------------- CSR build -----------------------------------------
__global__ void csr_count2(const int* __restrict__ iei, int Ei,
                           const int* __restrict__ fei, int Ef,
                           int* __restrict__ cnt)
{
    int i = blockIdx.x * blockDim.x + threadIdx.x;
    if (i < Ei) atomicAdd(&cnt[iei[Ei + i]], 1);
    else if (i < Ei + Ef) {
        int j = i - Ei;
        atomicAdd(&cnt[NN + fei[Ef + j]], 1);
    }
}

__global__ void __launch_bounds__(1024, 1)
csr_scan2(const int* __restrict__ cnt, int* __restrict__ off,
          int* __restrict__ cur, int base1)
{
    __shared__ int sa[1024], sbuf[1024];
    const int g = blockIdx.x;
    const int* c = cnt + g * NN;
    int* o = off + g * NN;
    int* u = cur + g * NN;
    int t = threadIdx.x;
    int base = t * 16;
    int loc[16];
    int s = 0;
#pragma unroll
    for (int j = 0; j < 16; j++) { loc[j] = c[base + j]; s += loc[j]; }
    sa[t] = s;
    __syncthreads();
    int* A = sa; int* Bf = sbuf;
    for (int d = 1; d < 1024; d <<= 1) {
        int v = A[t] + (t >= d ? A[t - d] : 0);
        __syncthreads();
        Bf[t] = v;
        __syncthreads();
        int* tmp = A; A = Bf; Bf = tmp;
    }
    int run = (t ? A[t - 1] : 0) + (g ? base1 : 0);
#pragma unroll
    for (int j = 0; j < 16; j++) { o[base + j] = run; u[base + j] = run; run += loc[j]; }
}

__global__ void csr_fill2(const int* __restrict__ iei, int Ei,
                          const int* __restrict__ fei, int Ef,
                          int* __restrict__ cur, int* __restrict__ srt)
{
    int i = blockIdx.x * blockDim.x + threadIdx.x;
    if (i < Ei) {
        int p = atomicAdd(&cur[iei[Ei + i]], 1);
        srt[p] = iei[i];
    } else if (i < Ei + Ef) {
        int j = i - Ei;
        int p = atomicAdd(&cur[NN + fei[Ef + j]], 1);
        srt[p] = fei[j];
    }
}

// gconv(int): Zg = leaky(M[r]+b+sum) + x_c ; emit split bf16 (ld 512)
__global__ void __launch_bounds__(128, 8)
gconv_int(const float* __restrict__ m, const float* __restrict__ bias,
          const int* __restrict__ off, const int* __restrict__ cnt,
          const int* __restrict__ srt,
          const float* __restrict__ x, const float* __restrict__ ko,
          __nv_bfloat16* __restrict__ Oh, __nv_bfloat16* __restrict__ Ol)
{
    const int r = blockIdx.x;
    const int t = threadIdx.x;
    float4 acc = reinterpret_cast<const float4*>(m + (size_t)r * DD)[t];
    float4 b   = reinterpret_cast<const float4*>(bias)[t];
    acc.x += b.x; acc.y += b.y; acc.z += b.z; acc.w += b.w;
    const int s0 = off[r];
    const int d  = cnt[r];
    for (int e = 0; e < d; e++) {
        int s = srt[s0 + e];
        float4 v = reinterpret_cast<const float4*>(m + (size_t)s * DD)[t];
        acc.x += v.x; acc.y += v.y; acc.z += v.z; acc.w += v.w;
    }
    acc.x = acc.x > 0.f ? acc.x : SLOPE_ * acc.x;
    acc.y = acc.y > 0.f ? acc.y : SLOPE_ * acc.y;
    acc.z = acc.z > 0.f ? acc.z : SLOPE_ * acc.z;
    acc.w = acc.w > 0.f ? acc.w : SLOPE_ * acc.w;
    const int c0 = t * 4;
    float vv[4] = {acc.x, acc.y, acc.z, acc.w};
#pragma unroll
    for (int q = 0; q < 4; q++) {
        int c = c0 + q;
        vv[q] += (c < OM_) ? x[(size_t)r * OM_ + c] : ko[r];
    }
    __nv_bfloat16 h[4], l[4];
#pragma unroll
    for (int q = 0; q < 4; q++) {
        h[q] = __float2bfloat16(vv[q]);
        l[q] = __float2bfloat16(vv[q] - __bfloat162float(h[q]));
    }
    size_t o = (size_t)r * DD + c0;
    __nv_bfloat162 h01; h01.x = h[0]; h01.y = h[1];
    __nv_bfloat162 h23; h23.x = h[2]; h23.y = h[3];
    __nv_bfloat162 l01; l01.x = l[0]; l01.y = l[1];
    __nv_bfloat162 l23; l23.x = l[2]; l23.y = l[3];
    *reinterpret_cast<__nv_bfloat162*>(Oh + o)     = h01;
    *reinterpret_cast<__nv_bfloat162*>(Oh + o + 2) = h23;
    *reinterpret_cast<__nv_bfloat162*>(Ol + o)     = l01;
    *reinterpret_cast<__nv_bfloat162*>(Ol + o + 2) = l23;
}

// gconv(full) only at the 1024 gathered KO rows; fused gather_zk
__global__ void __launch_bounds__(128, 8)
gconv_rows(const float* __restrict__ m, const float* __restrict__ bias,
           const int* __restrict__ off, const int* __restrict__ cnt,
           const int* __restrict__ srt, const int* __restrict__ bkm,
           float* __restrict__ ZK,
           __nv_bfloat16* __restrict__ Ah, __nv_bfloat16* __restrict__ Al)
{
    const int i = blockIdx.x;
    const int t = threadIdx.x;
    const int r = bkm[i] + (i >> 6) * NE_;
    float4 acc = reinterpret_cast<const float4*>(m + (size_t)r * DD)[t];
    float4 b   = reinterpret_cast<const float4*>(bias)[t];
    acc.x += b.x; acc.y += b.y; acc.z += b.z; acc.w += b.w;
    const int s0 = off[r];
    const int d  = cnt[r];
    for (int e = 0; e < d; e++) {
        int s = srt[s0 + e];
        float4 v = reinterpret_cast<const float4*>(m + (size_t)s * DD)[t];
        acc.x += v.x; acc.y += v.y; acc.z += v.z; acc.w += v.w;
    }
    acc.x = acc.x > 0.f ? acc.x : SLOPE_ * acc.x;
    acc.y = acc.y > 0.f ? acc.y : SLOPE_ * acc.y;
    acc.z = acc.z > 0.f ? acc.z : SLOPE_ * acc.z;
    acc.w = acc.w > 0.f ? acc.w : SLOPE_ * acc.w;
    reinterpret_cast<float4*>(ZK + (size_t)i * DD)[t] = acc;
    float vv[4] = {acc.x, acc.y, acc.z, acc.w};
    __nv_bfloat16 h[4], l[4];
#pragma unroll
    for (int q = 0; q < 4; q++) {
        h[q] = __float2bfloat16(vv[q]);
        l[q] = __float2bfloat16(vv[q] - __bfloat162float(h[q]));
    }
    size_t o = (size_t)i * DD + t * 4;
    __nv_bfloat162 h01; h01.x = h[0]; h01.y = h[1];
    __nv_bfloat162 h23; h23.x = h[2]; h23.y = h[3];
    __nv_bfloat162 l01; l01.x = l[0]; l01.y = l[1];
    __nv_bfloat162 l23; l23.x = l[2]; l23.y = l[3];
    *reinterpret_cast<__nv_bfloat162*>(Ah + o)     = h01;
    *reinterpret_cast<__nv_bfloat162*>(Ah + o + 2) = h23;
    *reinterpret_cast<__nv_bfloat162*>(Al + o)     = l01;
    *reinterpret_cast<__nv_bfloat162*>(Al + o + 2) = l23;
}

// ------------------------- readout -------------------------------------------
__global__ void tanh_dot(const float* __restrict__ H, const float* __restrict__ W2,
                         const float* __restrict__ b2, float* __restrict__ sc)
{
    int row = blockIdx.x;
    int tid = threadIdx.x;
    __shared__ float red[128];
    float p = 0.f;
    for (int j = tid; j < DD; j += 128)
        p = fmaf(tanhf(H[(size_t)row * DD + j]), W2[j], p);
    red[tid] = p;
    __syncthreads();
    for (int s = 64; s > 0; s >>= 1) {
        if (tid < s) red[tid] += red[tid + s];
        __syncthreads();
    }
    if (tid == 0) sc[row] = red[0] + b2[0];
}

__global__ void readout2(const float* __restrict__ ZK, const float* __restrict__ sc,
                         const float* __restrict__ regW, const float* __restrict__ regb,
                         float* __restrict__ out)
{
    int b = blockIdx.x;
    int tid = threadIdx.x;
    __shared__ float w[KK];
    __shared__ float red[256];
    __shared__ float sm;
    if (tid < KK) w[tid] = sc[b * KK + tid];
    __syncthreads();
    if (tid == 0) {
        float m = w[0];
        for (int k = 1; k < KK; k++) m = fmaxf(m, w[k]);
        float s = 0.f;
        for (int k = 0; k < KK; k++) { w[k] = expf(w[k] - m); s += w[k]; }
        sm = s;
    }
    __syncthreads();
    int c0 = tid, c1 = tid + 256;
    float r0 = 0.f, r1 = 0.f;
    for (int k = 0; k < KK; k++) {
        const float* z = ZK + ((size_t)b * KK + k) * DD;
        float wk = w[k];
        r0 = fmaf(wk, z[c0], r0);
        r1 = fmaf(wk, z[c1], r1);
    }
    float part = (r0 * regW[c0] + r1 * regW[c1]) / sm;
    red[tid] = part;
    __syncthreads();
    for (int s = 128; s > 0; s >>= 1) {
        if (tid < s) red[tid] += red[tid + s];
        __syncthreads();
    }
    if (tid == 0) out[b] = red[0] + regb[0];
}

// ------------------------- host side ------------------------------------------
static const int HG_SMEM = 2 * 40960;

extern "C" void kernel_launch(void* const* d_in, const int* in_sizes, int n_in,
                              void* d_out, int out_size)
{
    int map_[31];
    {
        int p = 0;
        for (int l = 0; l < 31; l++) {
            if (l == 5 || l == 8) {
                bool present = (n_in == 31);
                if (present && p < n_in && in_sizes[p] == 1) map_[l] = p++;
                else map_[l] = -1;
            } else map_[l] = p++;
        }
    }
    auto F = [&](int l) -> const float* { return (const float*)d_in[map_[l]]; };
    auto I = [&](int l) -> const int*   { return (const int*)d_in[map_[l]]; };

    const float* x        = F(0);
    const float* pre_x    = F(1);
    const int*   edge_ei  = I(2);
    const int*   int_ei   = I(3);
    const float* name_emb = F(6);
    const float* desc_emb = F(7);
    const int*   bkm      = I(9);
    const float* name_W = F(11), *name_b = F(12);
    const float* desc_W = F(13), *desc_b = F(14);
    const float* omic_W = F(15), *omic_b = F(16);
    const float* fus_W  = F(17), *fus_b  = F(18);
    const float* pre_W  = F(19), *pre_b  = F(20);
    const float* ienc_W = F(21), *ienc_b = F(22);
    const float* enc_W  = F(23), *enc_b  = F(24);
    const float* gate_W1 = F(25), *gate_b1 = F(26);
    const float* gate_W2 = F(27), *gate_b2 = F(28);
    const float* reg_W   = F(29), *reg_b   = F(30);
    float* out = (float*)d_out;

    const int E_full = in_sizes[map_[2]] / 2;
    const int E_int  = in_sizes[map_[3]] / 2;
    const float* W2 = fus_W + (size_t)1536 * OM_;

    __nv_bfloat16 *pA1H, *pA1L, *pA2H, *pA2L, *pCHH, *pCHL, *pE1H, *pE1L, *pE2H, *pE2L;
    __nv_bfloat16 *pWH, *pWL, *pWFH, *pWFL, *pNDPH, *pNDPL;
    float *pNDP2, *pB2, *pM, *pMP, *pZK, *pH, *pKO, *pSC;
    int *pCNT, *pOFF, *pCUR, *pSRT;
    cudaGetSymbolAddress((void**)&pA1H, g_A1H);
    cudaGetSymbolAddress((void**)&pA1L, g_A1L);
    cudaGetSymbolAddress((void**)&pA2H, g_A2H);
    cudaGetSymbolAddress((void**)&pA2L, g_A2L);
    cudaGetSymbolAddress((void**)&pCHH, g_CHH);
    cudaGetSymbolAddress((void**)&pCHL, g_CHL);
    cudaGetSymbolAddress((void**)&pE1H, g_E1H);
    cudaGetSymbolAddress((void**)&pE1L, g_E1L);
    cudaGetSymbolAddress((void**)&pE2H, g_E2H);
    cudaGetSymbolAddress((void**)&pE2L, g_E2L);
    cudaGetSymbolAddress((void**)&pWH,  g_WH);
    cudaGetSymbolAddress((void**)&pWL,  g_WL);
    cudaGetSymbolAddress((void**)&pWFH, g_WFH);
    cudaGetSymbolAddress((void**)&pWFL, g_WFL);
    cudaGetSymbolAddress((void**)&pNDPH, g_NDPH);
    cudaGetSymbolAddress((void**)&pNDPL, g_NDPL);
    cudaGetSymbolAddress((void**)&pNDP2, g_NDP2);
    cudaGetSymbolAddress((void**)&pB2,  g_B2);
    cudaGetSymbolAddress((void**)&pM,   g_M);
    cudaGetSymbolAddress((void**)&pMP,  g_MP);
    cudaGetSymbolAddress((void**)&pZK,  g_ZK);
    cudaGetSymbolAddress((void**)&pH,   g_H);
    cudaGetSymbolAddress((void**)&pKO,  g_KO);
    cudaGetSymbolAddress((void**)&pSC,  g_SC);
    cudaGetSymbolAddress((void**)&pCNT, g_CNT);
    cudaGetSymbolAddress((void**)&pOFF, g_OFF);
    cudaGetSymbolAddress((void**)&pCUR, g_CUR);
    cudaGetSymbolAddress((void**)&pSRT, g_SRT);

    cudaFuncSetAttribute(hgemm<0>,          cudaFuncAttributeMaxDynamicSharedMemorySize, HG_SMEM);
    cudaFuncSetAttribute(hgemm<2>,          cudaFuncAttributeMaxDynamicSharedMemorySize, HG_SMEM);
    cudaFuncSetAttribute(hgemm<32>,         cudaFuncAttributeMaxDynamicSharedMemorySize, HG_SMEM);
    cudaFuncSetAttribute(hgemm<4 | 32>,     cudaFuncAttributeMaxDynamicSharedMemorySize, HG_SMEM);
    cudaFuncSetAttribute(hgemm<8 | 16>,     cudaFuncAttributeMaxDynamicSharedMemorySize, HG_SMEM);
    cudaFuncSetAttribute(hgemm<1 | 8 | 16>, cudaFuncAttributeMaxDynamicSharedMemorySize, HG_SMEM);

    const long OFF_NAME  = 0;        // 768x768  name^T
    const long OFF_DESC  = 589824;   // 768x768  desc^T
    const long OFF_FUS1  = 1179648;  // 512x1536 fus[0:1536]^T
    const long OFF_OMIC  = 1966080;  // 512x512  omic^T
    const long OFF_IENC2 = 2228224;  // 512x512  ienc'^T
    const long OFF_W2D   = 2490368;  // 512x512  fus2 direct
    const long OFF_PRED  = 2752512;  // 512x512  pre_W direct
    const long OFF_ENC2  = 3014656;  // 512x1024 [enc^T | WPE^T]
    const long OFF_GATE  = 3538944;  // 512x512  gate1^T

    cudaStream_t s1, s2, s3;
    cudaStreamCreateWithFlags(&s1, cudaStreamNonBlocking);
    cudaStreamCreateWithFlags(&s2, cudaStreamNonBlocking);
    cudaStreamCreateWithFlags(&s3, cudaStreamNonBlocking);
    cudaEvent_t evStart, evW, evKO, ev1, ev2, ev3, evO0, evI0;
    cudaEventCreateWithFlags(&evStart, cudaEventDisableTiming);
    cudaEventCreateWithFlags(&evW,     cudaEventDisableTiming);
    cudaEventCreateWithFlags(&evKO,    cudaEventDisableTiming);
    cudaEventCreateWithFlags(&ev1,     cudaEventDisableTiming);
    cudaEventCreateWithFlags(&ev2,     cudaEventDisableTiming);
    cudaEventCreateWithFlags(&ev3,     cudaEventDisableTiming);
    cudaEventCreateWithFlags(&evO0,    cudaEventDisableTiming);
    cudaEventCreateWithFlags(&evI0,    cudaEventDisableTiming);

    cudaEventRecord(evStart, 0);
    cudaStreamWaitEvent(s1, evStart, 0);
    cudaStreamWaitEvent(s2, evStart, 0);

    // ---------------- s2: KO | CSR | pre split | M_pre ---------------------
    zero_f<<<(NN + 255) / 256, 256, 0, s2>>>(pKO, NN);
    set_ko<<<(BB * KK + 255) / 256, 256, 0, s2>>>(bkm, pKO);
    zero_i<<<(2 * NN + 255) / 256, 256, 0, s2>>>(pCNT, 2 * NN);
    csr_count2<<<(E_int + E_full + 255) / 256, 256, 0, s2>>>(int_ei, E_int, edge_ei, E_full, pCNT);
    csr_scan2<<<2, 1024, 0, s2>>>(pCNT, pOFF, pCUR, E_int);
    csr_fill2<<<(E_int + E_full + 255) / 256, 256, 0, s2>>>(int_ei, E_int, edge_ei, E_full, pCUR, pSRT);
    cudaEventRecord(evKO, s2);
    cvt_splitA<<<(NN * 256 + 255) / 256, 256, 0, s2>>>(pre_x, NN, OM_, OM_, 512, 512, pCHH, pCHL);

    // ---------------- s1: entity emb conversions ---------------------------
    cvt_splitA<<<(NE_ * 384 + 255) / 256, 256, 0, s1>>>(name_emb, NE_, TX_, TX_, TX_, TX_, pE1H, pE1L);
    cvt_splitA<<<(NE_ * 384 + 255) / 256, 256, 0, s1>>>(desc_emb, NE_, TX_, TX_, TX_, TX_,
                                                        pE1H + (size_t)NE_ * TX_,
                                                        pE1L + (size_t)NE_ * TX_);

    // ---------------- s0: x split + weight conversion ----------------------
    cvt_splitA<<<(NN * 256 + 255) / 256, 256>>>(x, NN, OM_, OM_, 512, 512, pA1H, pA1L);
    {
        WJobs jb;
        const float* Ws[9] = {name_W, desc_W, fus_W, omic_W, ienc_W, W2, pre_W, enc_W, gate_W1};
        int Ks[9]  = {TX_, TX_, 1536, OM_, OM_, OM_, DD, DD, DD};
        int Ns[9]  = {TX_, TX_, OM_, OM_, DD, OM_, DD, DD, DD};
        int ldw[9] = {TX_, TX_, OM_, OM_, DD, OM_, DD, DD, DD};
        int ldo[9] = {TX_, TX_, 1536, 512, 512, 512, 512, 1024, 512};
        int Np[9]  = {TX_, TX_, 512, 512, 512, 512, 512, 512, 512};
        int tr[9]  = {1, 1, 1, 1, 1, 0, 0, 1, 1};
        long offs[9] = {OFF_NAME, OFF_DESC, OFF_FUS1, OFF_OMIC, OFF_IENC2,
                        OFF_W2D, OFF_PRED, OFF_ENC2, OFF_GATE};
        long cum = 0;
        jb.njobs = 9;
        for (int j = 0; j < 9; j++) {
            jb.W[j] = Ws[j]; jb.K[j] = Ks[j]; jb.N[j] = Ns[j];
            jb.ldw[j] = ldw[j]; jb.ldo[j] = ldo[j]; jb.trans[j] = tr[j];
            jb.off[j] = offs[j];
            jb.cum[j] = cum; cum += (long)Np[j] * ldo[j];
        }
        jb.cum[9] = cum;
        cvt_splitW_all<<<(int)((cum + 255) / 256), 256>>>(jb, pWH, pWL);
    }
    cudaEventRecord(evW, 0);

    // ---------------- s3: WFT + WPE + fold_bias ----------------------------
    cudaStreamWaitEvent(s3, evW, 0);
    fold_bias<<<2, DD, 0, s3>>>(pre_b, pre_W, enc_W, pB2);
    hgemm<8 | 16><<<dim3(4, 4), 256, HG_SMEM, s3>>>(pWH + OFF_IENC2, pWL + OFF_IENC2,
        pWH + OFF_W2D, pWL + OFF_W2D,
        nullptr, nullptr, nullptr, nullptr, nullptr, nullptr, pWFH, pWFL,
        512, 512, 16, OM_, 0, 512, 512);
    hgemm<8 | 16><<<dim3(4, 4), 256, HG_SMEM, s3>>>(pWH + OFF_ENC2, pWL + OFF_ENC2,
        pWH + OFF_PRED, pWL + OFF_PRED,
        nullptr, nullptr, nullptr, nullptr, nullptr, nullptr,
        pWH + OFF_ENC2 + 512, pWL + OFF_ENC2 + 512,
        1024, 512, 16, 512, 0, 1024, 512);
    cudaEventRecord(ev3, s3);

    // ---------------- s2 (cont.): M_pre = pre_x@WPE + folds ----------------
    cudaStreamWaitEvent(s2, ev3, 0);
    hgemm<32><<<dim3(4, 128), 256, HG_SMEM, s2>>>(pCHH, pCHL,
        pWH + OFF_ENC2 + 512, pWL + OFF_ENC2 + 512,
        pB2, nullptr, pKO, pB2 + DD,
        nullptr, pMP, nullptr, nullptr,
        512, 1024, 16, DD, 512, 0, 0);
    cudaEventRecord(ev2, s2);

    // ---------------- s1 (cont.): entity GEMM chain ------------------------
    cudaStreamWaitEvent(s1, evW, 0);
    hgemm<1 | 8 | 16><<<dim3(6, 8), 256, HG_SMEM, s1>>>(pE1H, pE1L,
        pWH + OFF_NAME, pWL + OFF_NAME,
        name_b, nullptr, nullptr, nullptr, nullptr, nullptr, pE2H, pE2L,
        TX_, TX_, 24, TX_, 0, 1536, TX_);
    hgemm<1 | 8 | 16><<<dim3(6, 8), 256, HG_SMEM, s1>>>(pE1H + (size_t)NE_ * TX_,
        pE1L + (size_t)NE_ * TX_,
        pWH + OFF_DESC, pWL + OFF_DESC,
        desc_b, nullptr, nullptr, nullptr, nullptr, nullptr, pE2H + TX_, pE2L + TX_,
        TX_, TX_, 24, TX_, 0, 1536, TX_);
    hgemm<8 | 16><<<dim3(4, 8), 256, HG_SMEM, s1>>>(pE2H, pE2L,
        pWH + OFF_FUS1, pWL + OFF_FUS1,
        fus_b, nullptr, nullptr, nullptr, nullptr, nullptr, pNDPH, pNDPL,
        1536, 1536, 48, OM_, 0, 512, 512);
    hgemm<0><<<dim3(4, 8), 256, HG_SMEM, s1>>>(pNDPH, pNDPL,
        pWH + OFF_IENC2, pWL + OFF_IENC2,
        nullptr, nullptr, nullptr, nullptr, nullptr, pNDP2, nullptr, nullptr,
        512, 512, 16, DD, 512, 0, 0);
    cudaEventRecord(ev1, s1);

    // ---------------- s0: omic halves + overlapped ienc --------------------
    const size_t HOFF = (size_t)HALF_M * 512;
    // omic half 0
    hgemm<1 | 8 | 16><<<dim3(4, 64), 256, HG_SMEM>>>(pA1H, pA1L,
        pWH + OFF_OMIC, pWL + OFF_OMIC,
        omic_b, nullptr, nullptr, nullptr, nullptr, nullptr, pA2H, pA2L,
        512, 512, 16, OM_, 0, 512, 512);
    cudaEventRecord(evO0, 0);
    // omic half 1
    hgemm<1 | 8 | 16><<<dim3(4, 64), 256, HG_SMEM>>>(pA1H + HOFF, pA1L + HOFF,
        pWH + OFF_OMIC, pWL + OFF_OMIC,
        omic_b, nullptr, nullptr, nullptr, nullptr, nullptr, pA2H + HOFF, pA2L + HOFF,
        512, 512, 16, OM_, 0, 512, 512);

    // ienc half 0 on s1 (overlaps omic half 1)
    cudaStreamWaitEvent(s1, evO0, 0);
    cudaStreamWaitEvent(s1, ev3, 0);
    cudaStreamWaitEvent(s1, evKO, 0);
    hgemm<4 | 32><<<dim3(4, 64), 256, HG_SMEM, s1>>>(pA2H, pA2L, pWFH, pWFL,
        nullptr, pNDP2, pKO, ienc_W + (size_t)511 * DD,
        nullptr, pM, nullptr, nullptr,
        512, 512, 16, DD, 512, 0, 0);
    cudaEventRecord(evI0, s1);

    // ienc half 1 on s0 (after omic half 1, program order)
    cudaStreamWaitEvent(0, ev1, 0);
    cudaStreamWaitEvent(0, ev3, 0);
    cudaStreamWaitEvent(0, evKO, 0);
    hgemm<4 | 32><<<dim3(4, 64), 256, HG_SMEM>>>(pA2H + HOFF, pA2L + HOFF, pWFH, pWFL,
        nullptr, pNDP2, pKO + HALF_M, ienc_W + (size_t)511 * DD,
        nullptr, pM + HOFF, nullptr, nullptr,
        512, 512, 16, DD, 512, 0, 0);

    // gconv(int) needs ALL of M
    cudaStreamWaitEvent(0, evI0, 0);
    gconv_int<<<NN, 128>>>(pM, ienc_b, pOFF, pCNT, pSRT, x, pKO, pA2H, pA2L);

    // enc msg: M = Zg @ Wenc + M_pre (K=512; pre half precomputed)
    cudaStreamWaitEvent(0, ev2, 0);
    hgemm<2><<<dim3(4, 128), 256, HG_SMEM>>>(pA2H, pA2L,
        pWH + OFF_ENC2, pWL + OFF_ENC2,
        nullptr, nullptr, nullptr, nullptr,
        pMP, pM, nullptr, nullptr,
        512, 1024, 16, DD, 512, 0, 0);

    // gconv(full) at 1024 gathered rows only -> ZK fp32 + split for gate GEMM
    gconv_rows<<<BB * KK, 128>>>(pM, enc_b, pOFF + NN, pCNT + NN, pSRT, bkm,
                                 pZK, pA1H, pA1L);

    // gate GEMM + gated readout
    hgemm<0><<<dim3(4, 8), 256, HG_SMEM>>>(pA1H, pA1L,
        pWH + OFF_GATE, pWL + OFF_GATE,
        gate_b1, nullptr, nullptr, nullptr, nullptr, pH, nullptr, nullptr,
        512, 512, 16, DD, 512, 0, 0);
    tanh_dot<<<BB * KK, 128>>>(pH, gate_W2, gate_b2, pSC);
    readout2<<<BB, 256>>>(pZK, pSC, reg_W, reg_b, out);

    cudaStreamCaptureStatus cap = cudaStreamCaptureStatusNone;
    cudaStreamIsCapturing(0, &cap);
    if (cap == cudaStreamCaptureStatusNone) {
        cudaStreamDestroy(s1);
        cudaStreamDestroy(s2);
        cudaStreamDestroy(s3);
        cudaEventDestroy(evStart);
        cudaEventDestroy(evW);
        cudaEventDestroy(evKO);
        cudaEventDestroy(ev1);
        cudaEventDestroy(ev2);
        cudaEventDestroy(ev3);
        cudaEventDestroy(evO0);
        cudaEventDestroy(evI0);
    }

    (void)out_size;
    (void)n_in;
}

// round 14
// speedup vs baseline: 1.2060x; 1.0616x over previous
#include <cuda_runtime.h>
#include <cuda_bf16.h>
#include <cstdint>

#define NN      16384
#define NE_     1024
#define BB      16
#define KK      64
#define TX_     768
#define OM_     511
#define DD      512
#define SLOPE_  0.3f
#define E_INT_MAX 131072
#define E_FULL_MAX 262144
#define HALF_M  8192

// ------------------------- helpers ------------------------------------------
__device__ __forceinline__ uint32_t smem_to_u32(const void* p) {
    uint32_t a;
    asm("{ .reg .u64 t; cvta.to.shared.u64 t, %1; cvt.u32.u64 %0, t; }"
        : "=r"(a) : "l"(p));
    return a;
}

#define CP_ASYNC16(saddr, gptr) \
    asm volatile("cp.async.cg.shared.global [%0], [%1], 16;" \
                 :: "r"(saddr), "l"(gptr) : "memory")

#define LDMX4(r0, r1, r2, r3, addr) \
    asm volatile("ldmatrix.sync.aligned.m8n8.x4.shared.b16 {%0,%1,%2,%3}, [%4];" \
                 : "=r"(r0), "=r"(r1), "=r"(r2), "=r"(r3) : "r"(addr))

#define MMA16816(c, a, b) \
    asm volatile("mma.sync.aligned.m16n8k16.row.col.f32.bf16.bf16.f32 " \
                 "{%0,%1,%2,%3},{%4,%5,%6,%7},{%8,%9},{%0,%1,%2,%3};" \
                 : "+f"((c)[0]), "+f"((c)[1]), "+f"((c)[2]), "+f"((c)[3]) \
                 : "r"((a)[0]), "r"((a)[1]), "r"((a)[2]), "r"((a)[3]), \
                   "r"((b)[0]), "r"((b)[1]))

// ------------------------- scratch (device globals) -------------------------
__device__ __nv_bfloat16 g_A1H[NN * DD];       // x split; later ZK split
__device__ __nv_bfloat16 g_A1L[NN * DD];
__device__ __nv_bfloat16 g_A2H[NN * DD];       // omic split; later Zg split
__device__ __nv_bfloat16 g_A2L[NN * DD];
__device__ __nv_bfloat16 g_CHH[NN * DD];       // pre_x split
__device__ __nv_bfloat16 g_CHL[NN * DD];
__device__ __nv_bfloat16 g_E1H[2048 * TX_];    // entity emb split (name|desc)
__device__ __nv_bfloat16 g_E1L[2048 * TX_];
__device__ __nv_bfloat16 g_E2H[NE_ * 1536];    // entity linears split
__device__ __nv_bfloat16 g_E2L[NE_ * 1536];
#define WT_TOTAL 3801088
__device__ __nv_bfloat16 g_WH[WT_TOTAL];
__device__ __nv_bfloat16 g_WL[WT_TOTAL];
__device__ __nv_bfloat16 g_WFH[DD * DD];       // WFT split (ienc fold)
__device__ __nv_bfloat16 g_WFL[DD * DD];
__device__ __nv_bfloat16 g_NDPH[NE_ * DD];     // ndpart split
__device__ __nv_bfloat16 g_NDPL[NE_ * DD];
__device__ float g_NDP2[NE_ * DD];             // ndpart @ Wienc'
__device__ float g_B2  [2 * DD];               // [pre_b@Wenc | preW511@Wenc]
__device__ float g_M   [NN * DD];              // ienc message buffer
__device__ float g_MP  [NN * DD];              // M_pre, then enc message (in-place)
__device__ float g_ZK  [NE_ * DD];
__device__ float g_H   [NE_ * DD];
__device__ float g_KO  [NN];
__device__ float g_SC  [BB * KK];
__device__ int   g_CNT[2 * NN];
__device__ int   g_OFF[2 * NN];
__device__ int   g_CUR[2 * NN];
__device__ int   g_SRT[E_INT_MAX + E_FULL_MAX];

// ============================================================================
// HMMA split-bf16 GEMM, flag-specialized, one-sync pipelined mainloop.
// FLAGS: 1 leaky, 2 accumulate (+Cin), 4 add gat[(row&1023)*512+col],
//        8 write split-bf16 (Oh/Ol stride ldo, zero-pad cols [Nc,padN)),
//        16 skip fp32 C write, 32 add koV[row]*w511[col]
// ============================================================================
template <int FLAGS>
__global__ void __launch_bounds__(256, 2)
hgemm(const __nv_bfloat16* __restrict__ Ah, const __nv_bfloat16* __restrict__ Al,
      const __nv_bfloat16* __restrict__ Bh, const __nv_bfloat16* __restrict__ Bl,
      const float* __restrict__ bias, const float* __restrict__ gat,
      const float* __restrict__ koV, const float* __restrict__ w511,
      const float* __restrict__ Cin, float* __restrict__ C,
      __nv_bfloat16* __restrict__ Oh, __nv_bfloat16* __restrict__ Ol,
      int lda_b, int ldb_b, int nchunks, int Nc, int ldc, int ldo,
      int padN)
{
    extern __shared__ char smem[];
    const uint32_t sb = smem_to_u32(smem);
    const int tid  = threadIdx.x;
    const int lane = tid & 31;
    const int wid  = tid >> 5;
    const int wm   = (wid >> 2) * 64;
    const int wn   = (wid & 3) * 32;
    const int bm   = blockIdx.y * 128;
    const int bn   = blockIdx.x * 128;

    float acc[4][4][4];
#pragma unroll
    for (int i = 0; i < 4; i++)
#pragma unroll
        for (int j = 0; j < 4; j++)
#pragma unroll
            for (int q = 0; q < 4; q++) acc[i][j][q] = 0.f;

    auto load_stage = [&](int st, int k0) {
        const uint32_t base = sb + st * 40960;
#pragma unroll
        for (int i = 0; i < 2; i++) {
            const int idx = tid + i * 256;
            const int row = idx >> 2;
            const int c16 = idx & 3;
            const uint32_t so = base + row * 80 + c16 * 16;
            const size_t ga = (size_t)(bm + row) * lda_b + k0 + c16 * 8;
            const size_t gb = (size_t)(bn + row) * ldb_b + k0 + c16 * 8;
            CP_ASYNC16(so,          Ah + ga);
            CP_ASYNC16(so + 10240,  Al + ga);
            CP_ASYNC16(so + 20480,  Bh + gb);
            CP_ASYNC16(so + 30720,  Bl + gb);
        }
        asm volatile("cp.async.commit_group;" ::: "memory");
    };

    auto compute = [&](int st) {
        const uint32_t base = sb + st * 40960;
        const int arow = lane & 15;
        const int asub = (lane >> 4) * 8;
        const int brow = (lane & 7) + (lane >> 4) * 8;
        const int bsub = ((lane >> 3) & 1) * 8;
#pragma unroll
        for (int ks = 0; ks < 2; ks++) {
            const int kb = ks * 16;
            const uint32_t a0 = base + ((wm + arow) * 40 + kb + asub) * 2;
            const uint32_t b0 = base + 20480 + ((wn + brow) * 40 + kb + bsub) * 2;

            uint32_t ah[4][4], bh[4][2];
#pragma unroll
            for (int mt = 0; mt < 4; mt++)
                LDMX4(ah[mt][0], ah[mt][1], ah[mt][2], ah[mt][3], a0 + mt * 16 * 80);
#pragma unroll
            for (int p = 0; p < 2; p++)
                LDMX4(bh[2*p][0], bh[2*p][1], bh[2*p+1][0], bh[2*p+1][1],
                      b0 + p * 16 * 80);
#pragma unroll
            for (int mt = 0; mt < 4; mt++)
#pragma unroll
                for (int nt = 0; nt < 4; nt++)
                    MMA16816(acc[mt][nt], ah[mt], bh[nt]);
#pragma unroll
            for (int p = 0; p < 2; p++) {
                uint32_t bl[2][2];
                LDMX4(bl[0][0], bl[0][1], bl[1][0], bl[1][1],
                      b0 + 10240 + p * 16 * 80);
#pragma unroll
                for (int mt = 0; mt < 4; mt++) {
                    MMA16816(acc[mt][2*p],   ah[mt], bl[0]);
                    MMA16816(acc[mt][2*p+1], ah[mt], bl[1]);
                }
            }
#pragma unroll
            for (int mt = 0; mt < 4; mt++) {
                uint32_t al[4];
                LDMX4(al[0], al[1], al[2], al[3], a0 + 10240 + mt * 16 * 80);
#pragma unroll
                for (int nt = 0; nt < 4; nt++)
                    MMA16816(acc[mt][nt], al, bh[nt]);
            }
        }
    };

    load_stage(0, 0);
    for (int c = 0; c < nchunks; c++) {
        asm volatile("cp.async.wait_group 0;" ::: "memory");
        __syncthreads();
        if (c + 1 < nchunks) load_stage((c + 1) & 1, (c + 1) * 32);
        compute(c & 1);
    }

    // ---- epilogue ----
    const int er = lane >> 2;
    const int ec = (lane & 3) * 2;
#pragma unroll
    for (int mt = 0; mt < 4; mt++) {
#pragma unroll
        for (int h = 0; h < 2; h++) {
            const int row = bm + wm + mt * 16 + er + h * 8;
            const size_t crow = (size_t)row * ldc;
            const size_t orow = (size_t)row * ldo;
            const size_t grow = (size_t)(row & (NE_ - 1)) * 512;
            const float kv = (FLAGS & 32) ? koV[row] : 0.f;
#pragma unroll
            for (int nt = 0; nt < 4; nt++) {
                const int col = bn + wn + nt * 8 + ec;
                float v0 = acc[mt][nt][h * 2 + 0];
                float v1 = acc[mt][nt][h * 2 + 1];
                if (col + 1 < Nc) {
                    if (bias) {
                        float2 bb = *reinterpret_cast<const float2*>(bias + col);
                        v0 += bb.x; v1 += bb.y;
                    }
                    if (FLAGS & 4) {
                        float2 gg = *reinterpret_cast<const float2*>(gat + grow + col);
                        v0 += gg.x; v1 += gg.y;
                    }
                    if (FLAGS & 32) {
                        float2 ww = *reinterpret_cast<const float2*>(w511 + col);
                        v0 += kv * ww.x; v1 += kv * ww.y;
                    }
                    if (FLAGS & 1) {
                        v0 = v0 > 0.f ? v0 : SLOPE_ * v0;
                        v1 = v1 > 0.f ? v1 : SLOPE_ * v1;
                    }
                    if (FLAGS & 2) {
                        float2 ci = *reinterpret_cast<const float2*>(Cin + crow + col);
                        v0 += ci.x; v1 += ci.y;
                    }
                    if (!(FLAGS & 16))
                        *reinterpret_cast<float2*>(C + crow + col) = make_float2(v0, v1);
                    if (FLAGS & 8) {
                        __nv_bfloat16 h0 = __float2bfloat16(v0);
                        __nv_bfloat16 h1 = __float2bfloat16(v1);
                        __nv_bfloat162 hh; hh.x = h0; hh.y = h1;
                        __nv_bfloat162 ll;
                        ll.x = __float2bfloat16(v0 - __bfloat162float(h0));
                        ll.y = __float2bfloat16(v1 - __bfloat162float(h1));
                        *reinterpret_cast<__nv_bfloat162*>(Oh + orow + col) = hh;
                        *reinterpret_cast<__nv_bfloat162*>(Ol + orow + col) = ll;
                    }
                } else {
                    float vv[2] = {v0, v1};
#pragma unroll
                    for (int q = 0; q < 2; q++) {
                        const int cq = col + q;
                        if (cq < Nc) {
                            float v = vv[q];
                            if (bias)       v += bias[cq];
                            if (FLAGS & 4)  v += gat[grow + cq];
                            if (FLAGS & 32) v += kv * w511[cq];
                            if (FLAGS & 1)  v = v > 0.f ? v : SLOPE_ * v;
                            if (FLAGS & 2)  v += Cin[crow + cq];
                            if (!(FLAGS & 16)) C[crow + cq] = v;
                            if (FLAGS & 8) {
                                __nv_bfloat16 hh = __float2bfloat16(v);
                                Oh[orow + cq] = hh;
                                Ol[orow + cq] = __float2bfloat16(v - __bfloat162float(hh));
                            }
                        } else if ((FLAGS & 8) && cq < padN) {
                            Oh[orow + cq] = __float2bfloat16(0.f);
                            Ol[orow + cq] = __float2bfloat16(0.f);
                        }
                    }
                }
            }
        }
    }
}

// ------------------------- unified conversion kernel -------------------------
#define NJOBS 13
struct CJobs {
    const float* A[NJOBS];
    __nv_bfloat16* Oh[NJOBS];
    __nv_bfloat16* Ol[NJOBS];
    long cum[NJOBS + 1];          // in ELEMENT-PAIR units
    int Nv[NJOBS], K[NJOBS], lda[NJOBS], ldo[NJOBS], trans[NJOBS];
    int njobs;
};

__global__ void cvt_all(CJobs jb)
{
    long gid = (long)blockIdx.x * blockDim.x + threadIdx.x;
    if (gid >= jb.cum[jb.njobs]) return;
    int j = 0;
    while (gid >= jb.cum[j + 1]) j++;
    long local = gid - jb.cum[j];
    const int ldo = jb.ldo[j];
    const int ldo2 = ldo >> 1;
    const int n = (int)(local / ldo2);
    const int k = (int)(local - (long)n * ldo2) * 2;
    const float* A = jb.A[j];
    const int Nv = jb.Nv[j], K = jb.K[j], lda = jb.lda[j], tr = jb.trans[j];
    float v[2] = {0.f, 0.f};
#pragma unroll
    for (int q = 0; q < 2; q++) {
        const int kq = k + q;
        if (n < Nv && kq < K)
            v[q] = tr ? A[(size_t)kq * lda + n] : A[(size_t)n * lda + kq];
    }
    __nv_bfloat16 h0 = __float2bfloat16(v[0]), h1 = __float2bfloat16(v[1]);
    __nv_bfloat162 hh; hh.x = h0; hh.y = h1;
    __nv_bfloat162 ll;
    ll.x = __float2bfloat16(v[0] - __bfloat162float(h0));
    ll.y = __float2bfloat16(v[1] - __bfloat162float(h1));
    const size_t o = (size_t)n * ldo + k;
    *reinterpret_cast<__nv_bfloat162*>(jb.Oh[j] + o) = hh;
    *reinterpret_cast<__nv_bfloat162*>(jb.Ol[j] + o) = ll;
}

// B2[0,:] = pre_b @ enc_W ; B2[1,:] = pre_W[511,:] @ enc_W
__global__ void fold_bias(const float* __restrict__ pre_b, const float* __restrict__ pre_W,
                          const float* __restrict__ enc_W, float* __restrict__ B2)
{
    int n = threadIdx.x;
    int which = blockIdx.x;
    const float* v = which ? (pre_W + (size_t)511 * DD) : pre_b;
    float acc = 0.f;
    for (int j = 0; j < DD; j++)
        acc = fmaf(v[j], enc_W[(size_t)j * DD + n], acc);
    B2[which * DD + n] = acc;
}

// ------------------------- misc ----------------------------------------------
__global__ void zero_f(float* __restrict__ p, int n)
{ int i = blockIdx.x * blockDim.x + threadIdx.x; if (i < n) p[i] = 0.f; }
__global__ void zero_i(int* __restrict__ p, int n)
{ int i = blockIdx.x * blockDim.x + threadIdx.x; if (i < n) p[i] = 0; }

__global__ void set_ko(const int* __restrict__ bkm, float* __restrict__ ko)
{
    int i = blockIdx.x * blockDim.x + threadIdx.x;
    if (i < BB * KK) ko[(i >> 6) * NE_ + bkm[i]] = 1.0f;
}

// ------------------------- CSR build -----------------------------------------
__global__ void csr_count2(const int* __restrict__ iei, int Ei,
                           const int* __restrict__ fei, int Ef,
                           int* __restrict__ cnt)
{
    int i = blockIdx.x * blockDim.x + threadIdx.x;
    if (i < Ei) atomicAdd(&cnt[iei[Ei + i]], 1);
    else if (i < Ei + Ef) {
        int j = i - Ei;
        atomicAdd(&cnt[NN + fei[Ef + j]], 1);
    }
}

__global__ void __launch_bounds__(1024, 1)
csr_scan2(const int* __restrict__ cnt, int* __restrict__ off,
          int* __restrict__ cur, int base1)
{
    __shared__ int sa[1024], sbuf[1024];
    const int g = blockIdx.x;
    const int* c = cnt + g * NN;
    int* o = off + g * NN;
    int* u = cur + g * NN;
    int t = threadIdx.x;
    int base = t * 16;
    int loc[16];
    int s = 0;
#pragma unroll
    for (int j = 0; j < 16; j++) { loc[j] = c[base + j]; s += loc[j]; }
    sa[t] = s;
    __syncthreads();
    int* A = sa; int* Bf = sbuf;
    for (int d = 1; d < 1024; d <<= 1) {
        int v = A[t] + (t >= d ? A[t - d] : 0);
        __syncthreads();
        Bf[t] = v;
        __syncthreads();
        int* tmp = A; A = Bf; Bf = tmp;
    }
    int run = (t ? A[t - 1] : 0) + (g ? base1 : 0);
#pragma unroll
    for (int j = 0; j < 16; j++) { o[base + j] = run; u[base + j] = run; run += loc[j]; }
}

__global__ void csr_fill2(const int* __restrict__ iei, int Ei,
                          const int* __restrict__ fei, int Ef,
                          int* __restrict__ cur, int* __restrict__ srt)
{
    int i = blockIdx.x * blockDim.x + threadIdx.x;
    if (i < Ei) {
        int p = atomicAdd(&cur[iei[Ei + i]], 1);
        srt[p] = iei[i];
    } else if (i < Ei + Ef) {
        int j = i - Ei;
        int p = atomicAdd(&cur[NN + fei[Ef + j]], 1);
        srt[p] = fei[j];
    }
}

// gconv(int): Zg = leaky(M[r]+b+sum) + x_c ; emit split bf16 (ld 512); rbase offset
__global__ void __launch_bounds__(128, 8)
gconv_int(const float* __restrict__ m, const float* __restrict__ bias,
          const int* __restrict__ off, const int* __restrict__ cnt,
          const int* __restrict__ srt,
          const float* __restrict__ x, const float* __restrict__ ko,
          __nv_bfloat16* __restrict__ Oh, __nv_bfloat16* __restrict__ Ol,
          int rbase)
{
    const int r = blockIdx.x + rbase;
    const int t = threadIdx.x;
    float4 acc = reinterpret_cast<const float4*>(m + (size_t)r * DD)[t];
    float4 b   = reinterpret_cast<const float4*>(bias)[t];
    acc.x += b.x; acc.y += b.y; acc.z += b.z; acc.w += b.w;
    const int s0 = off[r];
    const int d  = cnt[r];
    for (int e = 0; e < d; e++) {
        int s = srt[s0 + e];
        float4 v = reinterpret_cast<const float4*>(m + (size_t)s * DD)[t];
        acc.x += v.x; acc.y += v.y; acc.z += v.z; acc.w += v.w;
    }
    acc.x = acc.x > 0.f ? acc.x : SLOPE_ * acc.x;
    acc.y = acc.y > 0.f ? acc.y : SLOPE_ * acc.y;
    acc.z = acc.z > 0.f ? acc.z : SLOPE_ * acc.z;
    acc.w = acc.w > 0.f ? acc.w : SLOPE_ * acc.w;
    const int c0 = t * 4;
    float vv[4] = {acc.x, acc.y, acc.z, acc.w};
#pragma unroll
    for (int q = 0; q < 4; q++) {
        int c = c0 + q;
        vv[q] += (c < OM_) ? x[(size_t)r * OM_ + c] : ko[r];
    }
    __nv_bfloat16 h[4], l[4];
#pragma unroll
    for (int q = 0; q < 4; q++) {
        h[q] = __float2bfloat16(vv[q]);
        l[q] = __float2bfloat16(vv[q] - __bfloat162float(h[q]));
    }
    size_t o = (size_t)r * DD + c0;
    __nv_bfloat162 h01; h01.x = h[0]; h01.y = h[1];
    __nv_bfloat162 h23; h23.x = h[2]; h23.y = h[3];
    __nv_bfloat162 l01; l01.x = l[0]; l01.y = l[1];
    __nv_bfloat162 l23; l23.x = l[2]; l23.y = l[3];
    *reinterpret_cast<__nv_bfloat162*>(Oh + o)     = h01;
    *reinterpret_cast<__nv_bfloat162*>(Oh + o + 2) = h23;
    *reinterpret_cast<__nv_bfloat162*>(Ol + o)     = l01;
    *reinterpret_cast<__nv_bfloat162*>(Ol + o + 2) = l23;
}

// gconv(full) only at the 1024 gathered KO rows; fused gather_zk
__global__ void __launch_bounds__(128, 8)
gconv_rows(const float* __restrict__ m, const float* __restrict__ bias,
           const int* __restrict__ off, const int* __restrict__ cnt,
           const int* __restrict__ srt, const int* __restrict__ bkm,
           float* __restrict__ ZK,
           __nv_bfloat16* __restrict__ Ah, __nv_bfloat16* __restrict__ Al)
{
    const int i = blockIdx.x;
    const int t = threadIdx.x;
    const int r = bkm[i] + (i >> 6) * NE_;
    float4 acc = reinterpret_cast<const float4*>(m + (size_t)r * DD)[t];
    float4 b   = reinterpret_cast<const float4*>(bias)[t];
    acc.x += b.x; acc.y += b.y; acc.z += b.z; acc.w += b.w;
    const int s0 = off[r];
    const int d  = cnt[r];
    for (int e = 0; e < d; e++) {
        int s = srt[s0 + e];
        float4 v = reinterpret_cast<const float4*>(m + (size_t)s * DD)[t];
        acc.x += v.x; acc.y += v.y; acc.z += v.z; acc.w += v.w;
    }
    acc.x = acc.x > 0.f ? acc.x : SLOPE_ * acc.x;
    acc.y = acc.y > 0.f ? acc.y : SLOPE_ * acc.y;
    acc.z = acc.z > 0.f ? acc.z : SLOPE_ * acc.z;
    acc.w = acc.w > 0.f ? acc.w : SLOPE_ * acc.w;
    reinterpret_cast<float4*>(ZK + (size_t)i * DD)[t] = acc;
    float vv[4] = {acc.x, acc.y, acc.z, acc.w};
    __nv_bfloat16 h[4], l[4];
#pragma unroll
    for (int q = 0; q < 4; q++) {
        h[q] = __float2bfloat16(vv[q]);
        l[q] = __float2bfloat16(vv[q] - __bfloat162float(h[q]));
    }
    size_t o = (size_t)i * DD + t * 4;
    __nv_bfloat162 h01; h01.x = h[0]; h01.y = h[1];
    __nv_bfloat162 h23; h23.x = h[2]; h23.y = h[3];
    __nv_bfloat162 l01; l01.x = l[0]; l01.y = l[1];
    __nv_bfloat162 l23; l23.x = l[2]; l23.y = l[3];
    *reinterpret_cast<__nv_bfloat162*>(Ah + o)     = h01;
    *reinterpret_cast<__nv_bfloat162*>(Ah + o + 2) = h23;
    *reinterpret_cast<__nv_bfloat162*>(Al + o)     = l01;
    *reinterpret_cast<__nv_bfloat162*>(Al + o + 2) = l23;
}

// ------------------------- readout -------------------------------------------
__global__ void tanh_dot(const float* __restrict__ H, const float* __restrict__ W2,
                         const float* __restrict__ b2, float* __restrict__ sc)
{
    int row = blockIdx.x;
    int tid = threadIdx.x;
    __shared__ float red[128];
    float p = 0.f;
    for (int j = tid; j < DD; j += 128)
        p = fmaf(tanhf(H[(size_t)row * DD + j]), W2[j], p);
    red[tid] = p;
    __syncthreads();
    for (int s = 64; s > 0; s >>= 1) {
        if (tid < s) red[tid] += red[tid + s];
        __syncthreads();
    }
    if (tid == 0) sc[row] = red[0] + b2[0];
}

__global__ void readout2(const float* __restrict__ ZK, const float* __restrict__ sc,
                         const float* __restrict__ regW, const float* __restrict__ regb,
                         float* __restrict__ out)
{
    int b = blockIdx.x;
    int tid = threadIdx.x;
    __shared__ float w[KK];
    __shared__ float red[256];
    __shared__ float sm;
    if (tid < KK) w[tid] = sc[b * KK + tid];
    __syncthreads();
    if (tid == 0) {
        float m = w[0];
        for (int k = 1; k < KK; k++) m = fmaxf(m, w[k]);
        float s = 0.f;
        for (int k = 0; k < KK; k++) { w[k] = expf(w[k] - m); s += w[k]; }
        sm = s;
    }
    __syncthreads();
    int c0 = tid, c1 = tid + 256;
    float r0 = 0.f, r1 = 0.f;
    for (int k = 0; k < KK; k++) {
        const float* z = ZK + ((size_t)b * KK + k) * DD;
        float wk = w[k];
        r0 = fmaf(wk, z[c0], r0);
        r1 = fmaf(wk, z[c1], r1);
    }
    float part = (r0 * regW[c0] + r1 * regW[c1]) / sm;
    red[tid] = part;
    __syncthreads();
    for (int s = 128; s > 0; s >>= 1) {
        if (tid < s) red[tid] += red[tid + s];
        __syncthreads();
    }
    if (tid == 0) out[b] = red[0] + regb[0];
}

// ------------------------- host side ------------------------------------------
static const int HG_SMEM = 2 * 40960;

extern "C" void kernel_launch(void* const* d_in, const int* in_sizes, int n_in,
                              void* d_out, int out_size)
{
    int map_[31];
    {
        int p = 0;
        for (int l = 0; l < 31; l++) {
            if (l == 5 || l == 8) {
                bool present = (n_in == 31);
                if (present && p < n_in && in_sizes[p] == 1) map_[l] = p++;
                else map_[l] = -1;
            } else map_[l] = p++;
        }
    }
    auto F = [&](int l) -> const float* { return (const float*)d_in[map_[l]]; };
    auto I = [&](int l) -> const int*   { return (const int*)d_in[map_[l]]; };

    const float* x        = F(0);
    const float* pre_x    = F(1);
    const int*   edge_ei  = I(2);
    const int*   int_ei   = I(3);
    const float* name_emb = F(6);
    const float* desc_emb = F(7);
    const int*   bkm      = I(9);
    const float* name_W = F(11), *name_b = F(12);
    const float* desc_W = F(13), *desc_b = F(14);
    const float* omic_W = F(15), *omic_b = F(16);
    const float* fus_W  = F(17), *fus_b  = F(18);
    const float* pre_W  = F(19), *pre_b  = F(20);
    const float* ienc_W = F(21), *ienc_b = F(22);
    const float* enc_W  = F(23), *enc_b  = F(24);
    const float* gate_W1 = F(25), *gate_b1 = F(26);
    const float* gate_W2 = F(27), *gate_b2 = F(28);
    const float* reg_W   = F(29), *reg_b   = F(30);
    float* out = (float*)d_out;

    const int E_full = in_sizes[map_[2]] / 2;
    const int E_int  = in_sizes[map_[3]] / 2;
    const float* W2 = fus_W + (size_t)1536 * OM_;

    __nv_bfloat16 *pA1H, *pA1L, *pA2H, *pA2L, *pCHH, *pCHL, *pE1H, *pE1L, *pE2H, *pE2L;
    __nv_bfloat16 *pWH, *pWL, *pWFH, *pWFL, *pNDPH, *pNDPL;
    float *pNDP2, *pB2, *pM, *pMP, *pZK, *pH, *pKO, *pSC;
    int *pCNT, *pOFF, *pCUR, *pSRT;
    cudaGetSymbolAddress((void**)&pA1H, g_A1H);
    cudaGetSymbolAddress((void**)&pA1L, g_A1L);
    cudaGetSymbolAddress((void**)&pA2H, g_A2H);
    cudaGetSymbolAddress((void**)&pA2L, g_A2L);
    cudaGetSymbolAddress((void**)&pCHH, g_CHH);
    cudaGetSymbolAddress((void**)&pCHL, g_CHL);
    cudaGetSymbolAddress((void**)&pE1H, g_E1H);
    cudaGetSymbolAddress((void**)&pE1L, g_E1L);
    cudaGetSymbolAddress((void**)&pE2H, g_E2H);
    cudaGetSymbolAddress((void**)&pE2L, g_E2L);
    cudaGetSymbolAddress((void**)&pWH,  g_WH);
    cudaGetSymbolAddress((void**)&pWL,  g_WL);
    cudaGetSymbolAddress((void**)&pWFH, g_WFH);
    cudaGetSymbolAddress((void**)&pWFL, g_WFL);
    cudaGetSymbolAddress((void**)&pNDPH, g_NDPH);
    cudaGetSymbolAddress((void**)&pNDPL, g_NDPL);
    cudaGetSymbolAddress((void**)&pNDP2, g_NDP2);
    cudaGetSymbolAddress((void**)&pB2,  g_B2);
    cudaGetSymbolAddress((void**)&pM,   g_M);
    cudaGetSymbolAddress((void**)&pMP,  g_MP);
    cudaGetSymbolAddress((void**)&pZK,  g_ZK);
    cudaGetSymbolAddress((void**)&pH,   g_H);
    cudaGetSymbolAddress((void**)&pKO,  g_KO);
    cudaGetSymbolAddress((void**)&pSC,  g_SC);
    cudaGetSymbolAddress((void**)&pCNT, g_CNT);
    cudaGetSymbolAddress((void**)&pOFF, g_OFF);
    cudaGetSymbolAddress((void**)&pCUR, g_CUR);
    cudaGetSymbolAddress((void**)&pSRT, g_SRT);

    cudaFuncSetAttribute(hgemm<0>,          cudaFuncAttributeMaxDynamicSharedMemorySize, HG_SMEM);
    cudaFuncSetAttribute(hgemm<2>,          cudaFuncAttributeMaxDynamicSharedMemorySize, HG_SMEM);
    cudaFuncSetAttribute(hgemm<32>,         cudaFuncAttributeMaxDynamicSharedMemorySize, HG_SMEM);
    cudaFuncSetAttribute(hgemm<4 | 32>,     cudaFuncAttributeMaxDynamicSharedMemorySize, HG_SMEM);
    cudaFuncSetAttribute(hgemm<8 | 16>,     cudaFuncAttributeMaxDynamicSharedMemorySize, HG_SMEM);
    cudaFuncSetAttribute(hgemm<1 | 8 | 16>, cudaFuncAttributeMaxDynamicSharedMemorySize, HG_SMEM);

    const long OFF_NAME  = 0;
    const long OFF_DESC  = 589824;
    const long OFF_FUS1  = 1179648;
    const long OFF_OMIC  = 1966080;
    const long OFF_IENC2 = 2228224;
    const long OFF_W2D   = 2490368;
    const long OFF_PRED  = 2752512;
    const long OFF_ENC2  = 3014656;
    const long OFF_GATE  = 3538944;

    cudaStream_t s1, s2, s3;
    cudaStreamCreateWithFlags(&s1, cudaStreamNonBlocking);
    cudaStreamCreateWithFlags(&s2, cudaStreamNonBlocking);
    cudaStreamCreateWithFlags(&s3, cudaStreamNonBlocking);
    cudaEvent_t evStart, evW, evKO, ev1, ev2, ev3, evO0, evI0, evI1, evG1;
    cudaEventCreateWithFlags(&evStart, cudaEventDisableTiming);
    cudaEventCreateWithFlags(&evW,     cudaEventDisableTiming);
    cudaEventCreateWithFlags(&evKO,    cudaEventDisableTiming);
    cudaEventCreateWithFlags(&ev1,     cudaEventDisableTiming);
    cudaEventCreateWithFlags(&ev2,     cudaEventDisableTiming);
    cudaEventCreateWithFlags(&ev3,     cudaEventDisableTiming);
    cudaEventCreateWithFlags(&evO0,    cudaEventDisableTiming);
    cudaEventCreateWithFlags(&evI0,    cudaEventDisableTiming);
    cudaEventCreateWithFlags(&evI1,    cudaEventDisableTiming);
    cudaEventCreateWithFlags(&evG1,    cudaEventDisableTiming);

    cudaEventRecord(evStart, 0);
    cudaStreamWaitEvent(s2, evStart, 0);

    // ---------------- s2: KO | CSR ------------------------------------------
    zero_f<<<(NN + 255) / 256, 256, 0, s2>>>(pKO, NN);
    set_ko<<<(BB * KK + 255) / 256, 256, 0, s2>>>(bkm, pKO);
    zero_i<<<(2 * NN + 255) / 256, 256, 0, s2>>>(pCNT, 2 * NN);
    csr_count2<<<(E_int + E_full + 255) / 256, 256, 0, s2>>>(int_ei, E_int, edge_ei, E_full, pCNT);
    csr_scan2<<<2, 1024, 0, s2>>>(pCNT, pOFF, pCUR, E_int);
    csr_fill2<<<(E_int + E_full + 255) / 256, 256, 0, s2>>>(int_ei, E_int, edge_ei, E_full, pCUR, pSRT);
    cudaEventRecord(evKO, s2);

    // ---------------- s0: unified conversion (all inputs + weights) ---------
    {
        CJobs jb;
        const float* As[NJOBS] = {x, pre_x, name_emb, desc_emb,
                                  name_W, desc_W, fus_W, omic_W, ienc_W,
                                  W2, pre_W, enc_W, gate_W1};
        __nv_bfloat16* Ohs[NJOBS] = {pA1H, pCHH, pE1H, pE1H + (size_t)NE_ * TX_,
                                     pWH + OFF_NAME, pWH + OFF_DESC, pWH + OFF_FUS1,
                                     pWH + OFF_OMIC, pWH + OFF_IENC2, pWH + OFF_W2D,
                                     pWH + OFF_PRED, pWH + OFF_ENC2, pWH + OFF_GATE};
        __nv_bfloat16* Ols[NJOBS] = {pA1L, pCHL, pE1L, pE1L + (size_t)NE_ * TX_,
                                     pWL + OFF_NAME, pWL + OFF_DESC, pWL + OFF_FUS1,
                                     pWL + OFF_OMIC, pWL + OFF_IENC2, pWL + OFF_W2D,
                                     pWL + OFF_PRED, pWL + OFF_ENC2, pWL + OFF_GATE};
        int Nvs[NJOBS]  = {NN, NN, NE_, NE_, TX_, TX_, OM_, OM_, DD, OM_, DD, DD, DD};
        int Ks[NJOBS]   = {OM_, OM_, TX_, TX_, TX_, TX_, 1536, OM_, OM_, OM_, DD, DD, DD};
        int ldas[NJOBS] = {OM_, OM_, TX_, TX_, TX_, TX_, OM_, OM_, DD, OM_, DD, DD, DD};
        int ldos[NJOBS] = {512, 512, TX_, TX_, TX_, TX_, 1536, 512, 512, 512, 512, 1024, 512};
        int Nps[NJOBS]  = {NN, NN, NE_, NE_, TX_, TX_, 512, 512, 512, 512, 512, 512, 512};
        int trs[NJOBS]  = {0, 0, 0, 0, 1, 1, 1, 1, 1, 0, 0, 1, 1};
        long cum = 0;
        jb.njobs = NJOBS;
        for (int j = 0; j < NJOBS; j++) {
            jb.A[j] = As[j]; jb.Oh[j] = Ohs[j]; jb.Ol[j] = Ols[j];
            jb.Nv[j] = Nvs[j]; jb.K[j] = Ks[j]; jb.lda[j] = ldas[j];
            jb.ldo[j] = ldos[j]; jb.trans[j] = trs[j];
            jb.cum[j] = cum;
            cum += (long)Nps[j] * (ldos[j] >> 1);
        }
        jb.cum[NJOBS] = cum;
        cvt_all<<<(int)((cum + 255) / 256), 256>>>(jb);
    }
    cudaEventRecord(evW, 0);

    // ---------------- s3: WFT + WPE + fold_bias ------------------------------
    cudaStreamWaitEvent(s3, evW, 0);
    fold_bias<<<2, DD, 0, s3>>>(pre_b, pre_W, enc_W, pB2);
    hgemm<8 | 16><<<dim3(4, 4), 256, HG_SMEM, s3>>>(pWH + OFF_IENC2, pWL + OFF_IENC2,
        pWH + OFF_W2D, pWL + OFF_W2D,
        nullptr, nullptr, nullptr, nullptr, nullptr, nullptr, pWFH, pWFL,
        512, 512, 16, OM_, 0, 512, 512);
    hgemm<8 | 16><<<dim3(4, 4), 256, HG_SMEM, s3>>>(pWH + OFF_ENC2, pWL + OFF_ENC2,
        pWH + OFF_PRED, pWL + OFF_PRED,
        nullptr, nullptr, nullptr, nullptr, nullptr, nullptr,
        pWH + OFF_ENC2 + 512, pWL + OFF_ENC2 + 512,
        1024, 512, 16, 512, 0, 1024, 512);
    cudaEventRecord(ev3, s3);

    // ---------------- s2 (cont.): M_pre = pre_x@WPE + folds -> MP -----------
    cudaStreamWaitEvent(s2, ev3, 0);
    hgemm<32><<<dim3(4, 128), 256, HG_SMEM, s2>>>(pCHH, pCHL,
        pWH + OFF_ENC2 + 512, pWL + OFF_ENC2 + 512,
        pB2, nullptr, pKO, pB2 + DD,
        nullptr, pMP, nullptr, nullptr,
        512, 1024, 16, DD, 512, 0, 0);
    cudaEventRecord(ev2, s2);

    // ---------------- s1: entity GEMM chain ----------------------------------
    cudaStreamWaitEvent(s1, evW, 0);
    hgemm<1 | 8 | 16><<<dim3(6, 8), 256, HG_SMEM, s1>>>(pE1H, pE1L,
        pWH + OFF_NAME, pWL + OFF_NAME,
        name_b, nullptr, nullptr, nullptr, nullptr, nullptr, pE2H, pE2L,
        TX_, TX_, 24, TX_, 0, 1536, TX_);
    hgemm<1 | 8 | 16><<<dim3(6, 8), 256, HG_SMEM, s1>>>(pE1H + (size_t)NE_ * TX_,
        pE1L + (size_t)NE_ * TX_,
        pWH + OFF_DESC, pWL + OFF_DESC,
        desc_b, nullptr, nullptr, nullptr, nullptr, nullptr, pE2H + TX_, pE2L + TX_,
        TX_, TX_, 24, TX_, 0, 1536, TX_);
    hgemm<8 | 16><<<dim3(4, 8), 256, HG_SMEM, s1>>>(pE2H, pE2L,
        pWH + OFF_FUS1, pWL + OFF_FUS1,
        fus_b, nullptr, nullptr, nullptr, nullptr, nullptr, pNDPH, pNDPL,
        1536, 1536, 48, OM_, 0, 512, 512);
    hgemm<0><<<dim3(4, 8), 256, HG_SMEM, s1>>>(pNDPH, pNDPL,
        pWH + OFF_IENC2, pWL + OFF_IENC2,
        nullptr, nullptr, nullptr, nullptr, nullptr, pNDP2, nullptr, nullptr,
        512, 512, 16, DD, 512, 0, 0);
    cudaEventRecord(ev1, s1);

    // ---------------- s0: omic halves + overlapped ienc ----------------------
    const size_t HOFF = (size_t)HALF_M * 512;
    hgemm<1 | 8 | 16><<<dim3(4, 64), 256, HG_SMEM>>>(pA1H, pA1L,
        pWH + OFF_OMIC, pWL + OFF_OMIC,
        omic_b, nullptr, nullptr, nullptr, nullptr, nullptr, pA2H, pA2L,
        512, 512, 16, OM_, 0, 512, 512);
    cudaEventRecord(evO0, 0);
    hgemm<1 | 8 | 16><<<dim3(4, 64), 256, HG_SMEM>>>(pA1H + HOFF, pA1L + HOFF,
        pWH + OFF_OMIC, pWL + OFF_OMIC,
        omic_b, nullptr, nullptr, nullptr, nullptr, nullptr, pA2H + HOFF, pA2L + HOFF,
        512, 512, 16, OM_, 0, 512, 512);

    // ienc half 0 on s1 (overlaps omic half 1)
    cudaStreamWaitEvent(s1, evO0, 0);
    cudaStreamWaitEvent(s1, ev3, 0);
    cudaStreamWaitEvent(s1, evKO, 0);
    hgemm<4 | 32><<<dim3(4, 64), 256, HG_SMEM, s1>>>(pA2H, pA2L, pWFH, pWFL,
        nullptr, pNDP2, pKO, ienc_W + (size_t)511 * DD,
        nullptr, pM, nullptr, nullptr,
        512, 512, 16, DD, 512, 0, 0);
    cudaEventRecord(evI0, s1);

    // ienc half 1 on s0
    cudaStreamWaitEvent(0, ev1, 0);
    cudaStreamWaitEvent(0, ev3, 0);
    cudaStreamWaitEvent(0, evKO, 0);
    hgemm<4 | 32><<<dim3(4, 64), 256, HG_SMEM>>>(pA2H + HOFF, pA2L + HOFF, pWFH, pWFL,
        nullptr, pNDP2, pKO + HALF_M, ienc_W + (size_t)511 * DD,
        nullptr, pM + HOFF, nullptr, nullptr,
        512, 512, 16, DD, 512, 0, 0);
    cudaEventRecord(evI1, 0);

    // gconv halves (each needs ALL of M)
    cudaStreamWaitEvent(0, evI0, 0);
    gconv_int<<<HALF_M, 128>>>(pM, ienc_b, pOFF, pCNT, pSRT, x, pKO, pA2H, pA2L, 0);

    cudaStreamWaitEvent(s1, evI1, 0);
    gconv_int<<<HALF_M, 128, 0, s1>>>(pM, ienc_b, pOFF, pCNT, pSRT, x, pKO,
                                      pA2H, pA2L, HALF_M);
    cudaEventRecord(evG1, s1);

    // enc half 0 (Zg rows 0..HALF_M-1; accumulate into MP in place) overlaps gconv_h1
    cudaStreamWaitEvent(0, ev2, 0);
    hgemm<2><<<dim3(4, 64), 256, HG_SMEM>>>(pA2H, pA2L,
        pWH + OFF_ENC2, pWL + OFF_ENC2,
        nullptr, nullptr, nullptr, nullptr,
        pMP, pMP, nullptr, nullptr,
        512, 1024, 16, DD, 512, 0, 0);
    // enc half 1
    cudaStreamWaitEvent(0, evG1, 0);
    hgemm<2><<<dim3(4, 64), 256, HG_SMEM>>>(pA2H + HOFF, pA2L + HOFF,
        pWH + OFF_ENC2, pWL + OFF_ENC2,
        nullptr, nullptr, nullptr, nullptr,
        pMP + HOFF, pMP + HOFF, nullptr, nullptr,
        512, 1024, 16, DD, 512, 0, 0);

    // gconv(full) at 1024 gathered rows -> ZK fp32 + split for gate GEMM
    gconv_rows<<<BB * KK, 128>>>(pMP, enc_b, pOFF + NN, pCNT + NN, pSRT, bkm,
                                 pZK, pA1H, pA1L);

    // gate GEMM + gated readout
    hgemm<0><<<dim3(4, 8), 256, HG_SMEM>>>(pA1H, pA1L,
        pWH + OFF_GATE, pWL + OFF_GATE,
        gate_b1, nullptr, nullptr, nullptr, nullptr, pH, nullptr, nullptr,
        512, 512, 16, DD, 512, 0, 0);
    tanh_dot<<<BB * KK, 128>>>(pH, gate_W2, gate_b2, pSC);
    readout2<<<BB, 256>>>(pZK, pSC, reg_W, reg_b, out);

    cudaStreamCaptureStatus cap = cudaStreamCaptureStatusNone;
    cudaStreamIsCapturing(0, &cap);
    if (cap == cudaStreamCaptureStatusNone) {
        cudaStreamDestroy(s1);
        cudaStreamDestroy(s2);
        cudaStreamDestroy(s3);
        cudaEventDestroy(evStart);
        cudaEventDestroy(evW);
        cudaEventDestroy(evKO);
        cudaEventDestroy(ev1);
        cudaEventDestroy(ev2);
        cudaEventDestroy(ev3);
        cudaEventDestroy(evO0);
        cudaEventDestroy(evI0);
        cudaEventDestroy(evI1);
        cudaEventDestroy(evG1);
    }

    (void)out_size;
    (void)n_in;
}